// round 10
// baseline (speedup 1.0000x reference)
#include <cuda_runtime.h>
#include <math.h>
#include <stdint.h>

#define NPOS 16384      // HRV*WRV = 32*512
#define NQ   81920      // NPOS*K
#define NV   65536      // HB*WB = 256*256
#define NBINS 110
#define HEADS 8
#define NSLAB 64

// ---------------- scratch (single __device__ arena, no allocations) -------
constexpr size_t O_Q0   = 0;
constexpr size_t O_CAT1 = O_Q0   + (size_t)NPOS*128;
constexpr size_t O_H1   = O_CAT1 + (size_t)NPOS*67;
constexpr size_t O_H2   = O_H1   + (size_t)NPOS*128;
constexpr size_t O_LG   = O_H2   + (size_t)NPOS*64;
constexpr size_t O_DEP  = O_LG   + (size_t)NPOS*110;
constexpr size_t O_WGT  = O_DEP  + (size_t)NPOS*5;
constexpr size_t O_REF  = O_WGT  + (size_t)NPOS*5;
constexpr size_t O_QIN  = O_REF  + (size_t)NQ*2;
constexpr size_t O_QMID = O_QIN  + (size_t)NQ*129;
constexpr size_t O_QRY  = O_QMID + (size_t)NQ*128;
constexpr size_t O_MEAN = O_QRY  + (size_t)NQ*128;
constexpr size_t O_RSTD = O_MEAN + 8;
constexpr size_t O_GNP  = O_RSTD + 8;                 // 8 groups*64 slabs*1 double
constexpr size_t O_VMAP = O_GNP  + 1024;
constexpr size_t O_V    = O_VMAP + (size_t)NV*128;
constexpr size_t O_OFF  = O_V    + (size_t)NV*128;
constexpr size_t O_AW   = O_OFF  + (size_t)NQ*96;
constexpr size_t O_SAMP = O_AW   + (size_t)NQ*48;
constexpr size_t O_MSDA = O_SAMP + (size_t)NQ*128;
constexpr size_t O_YK   = O_MSDA + (size_t)NQ*128;
constexpr size_t TOTALF = O_YK   + (size_t)NPOS*128;
static_assert((O_V & 3) == 0 && (O_SAMP & 3) == 0 && (O_GNP & 1) == 0, "align");

__device__ float g_scratch[TOTALF];

__constant__ float c_elev_deg[32] = {
    -30.67f, -29.33f, -28.0f, -26.66f, -25.33f, -24.0f, -22.67f, -21.33f,
    -20.0f, -18.67f, -17.33f, -16.0f, -14.67f, -13.33f, -12.0f, -10.67f,
    -9.33f, -8.0f, -6.66f, -5.33f, -4.0f, -2.67f, -1.33f, 0.0f, 1.33f,
    2.67f, 4.0f, 5.33f, 6.67f, 8.0f, 9.33f, 10.67f};

// IEEE round-to-nearest fp32 division (immune to any fast-math flags)
__device__ __forceinline__ float fdiv_rn(float a, float b) {
    float r;
    asm("div.rn.f32 %0, %1, %2;" : "=f"(r) : "f"(a), "f"(b));
    return r;
}

// XLA EmitErfF32 == Eigen generic_fast_erf_float: rational poly, clamp +-4.
__device__ __forceinline__ float erf_xla(float x) {
    x = fmaxf(fminf(x, 4.f), -4.f);
    float x2 = x * x;
    float p = fmaf(x2, -2.72614225801306e-10f, 2.77068142495902e-08f);
    p = fmaf(x2, p, -2.10102402082508e-06f);
    p = fmaf(x2, p, -5.69250639462346e-05f);
    p = fmaf(x2, p, -7.34990630326855e-04f);
    p = fmaf(x2, p, -2.95459980854025e-03f);
    p = fmaf(x2, p, -1.60960333262415e-02f);
    p = x * p;
    float q = fmaf(x2, -1.45660718464996e-05f, -2.13374055278905e-04f);
    q = fmaf(x2, q, -1.68282697438203e-03f);
    q = fmaf(x2, q, -7.37332916720468e-03f);
    q = fmaf(x2, q, -1.42647390514189e-02f);
    return fdiv_rn(p, q);
}

__device__ __forceinline__ float gelu_xla(float x) {
    float e = erf_xla(fdiv_rn(x, 1.4142135623730951f));
    return 0.5f * x * (1.f + e);
}

// Exactly-compensated accumulate of a*b into (s, c): error O(eps^2).
__device__ __forceinline__ void acc2(float a, float b, float& s, float& c) {
    float p = a * b;
    float e = fmaf(a, b, -p);
    float t = s + p;
    float z = t - s;
    c += ((s - (t - z)) + (p - z)) + e;
    s = t;
}

// ---------------- legacy SGEMM (COMP depth-path GEMMs — FROZEN) ------------
template <int EPI, bool AT, bool COMP>
__global__ void sgemm(const float* __restrict__ A, const float* __restrict__ W,
                      const float* __restrict__ bias, const float* __restrict__ Cadd,
                      float* __restrict__ C, int M, int N, int K, int lda) {
    __shared__ float As[16][68];
    __shared__ float Bs[16][68];
    int bm = blockIdx.y * 64, bn = blockIdx.x * 64;
    int tid = threadIdx.x;
    int tx = tid & 15, ty = tid >> 4;
    float acc[4][4] = {};
    float cmp[4][4] = {};
    for (int k0 = 0; k0 < K; k0 += 16) {
#pragma unroll
        for (int i = 0; i < 4; i++) {
            int e = tid + i * 256;
            int kl, ml;
            if (AT) { ml = e & 63; kl = e >> 6; }
            else    { kl = e & 15; ml = e >> 4; }
            int m = bm + ml, k = k0 + kl;
            float v = 0.f;
            if (m < M && k < K)
                v = AT ? A[(size_t)k * lda + m] : A[(size_t)m * lda + k];
            As[kl][ml] = v;
        }
#pragma unroll
        for (int i = 0; i < 4; i++) {
            int e = tid + i * 256;
            int kl = e & 15, nl = e >> 4;
            int n = bn + nl, k = k0 + kl;
            Bs[kl][nl] = (n < N && k < K) ? W[(size_t)n * K + k] : 0.f;
        }
        __syncthreads();
#pragma unroll
        for (int kk = 0; kk < 16; kk++) {
            float4 ra = *(const float4*)&As[kk][ty * 4];
            float4 rb = *(const float4*)&Bs[kk][tx * 4];
            float a[4] = {ra.x, ra.y, ra.z, ra.w};
            float b[4] = {rb.x, rb.y, rb.z, rb.w};
#pragma unroll
            for (int i = 0; i < 4; i++)
#pragma unroll
                for (int j = 0; j < 4; j++) {
                    if (COMP) acc2(a[i], b[j], acc[i][j], cmp[i][j]);
                    else acc[i][j] += a[i] * b[j];
                }
        }
        __syncthreads();
    }
#pragma unroll
    for (int i = 0; i < 4; i++) {
        int m = bm + ty * 4 + i;
        if (m >= M) continue;
#pragma unroll
        for (int j = 0; j < 4; j++) {
            int n = bn + tx * 4 + j;
            if (n >= N) continue;
            float v = (COMP ? (acc[i][j] + cmp[i][j]) : acc[i][j]) + bias[n];
            if (EPI == 1) v = gelu_xla(v);
            if (EPI == 2) v += Cadd[(size_t)m * N + n];
            C[(size_t)m * N + n] = v;
        }
    }
}

// ---------------- fast SGEMM: 128x64 tile, 8x4 micro (small-N cases) -------
template <int EPI, bool AT>
__global__ void __launch_bounds__(256, 2)
sgemm_fast(const float* __restrict__ A, const float* __restrict__ W,
           const float* __restrict__ bias, const float* __restrict__ Cadd,
           float* __restrict__ C, int M, int N, int K, int lda) {
    __shared__ float As[2][16][132];
    __shared__ float Bs[2][16][68];
    const int bm = blockIdx.y * 128, bn = blockIdx.x * 64;
    const int tid = threadIdx.x;
    const int tx = tid & 15;
    const int ty = tid >> 4;
    float acc[8][4] = {};

    auto load_stage = [&](int buf, int k0) {
#pragma unroll
        for (int i = 0; i < 8; i++) {
            int e = tid + i * 256;
            int kl, ml;
            if (AT) { ml = e & 127; kl = e >> 7; }
            else    { kl = e & 15;  ml = e >> 4; }
            int m = bm + ml, k = k0 + kl;
            float v = 0.f;
            if (m < M && k < K)
                v = AT ? A[(size_t)k * lda + m] : A[(size_t)m * lda + k];
            As[buf][kl][ml] = v;
        }
#pragma unroll
        for (int i = 0; i < 4; i++) {
            int e = tid + i * 256;
            int kl = e & 15, nl = e >> 4;
            int n = bn + nl, k = k0 + kl;
            Bs[buf][kl][nl] = (n < N && k < K) ? W[(size_t)n * K + k] : 0.f;
        }
    };

    const int nk = (K + 15) >> 4;
    load_stage(0, 0);
    __syncthreads();
    for (int t = 0; t < nk; t++) {
        int cur = t & 1;
        if (t + 1 < nk) load_stage(cur ^ 1, (t + 1) * 16);
#pragma unroll
        for (int kk = 0; kk < 16; kk++) {
            float4 a0 = *(const float4*)&As[cur][kk][ty * 8];
            float4 a1 = *(const float4*)&As[cur][kk][ty * 8 + 4];
            float4 b0 = *(const float4*)&Bs[cur][kk][tx * 4];
            float a[8] = {a0.x, a0.y, a0.z, a0.w, a1.x, a1.y, a1.z, a1.w};
            float b[4] = {b0.x, b0.y, b0.z, b0.w};
#pragma unroll
            for (int i = 0; i < 8; i++)
#pragma unroll
                for (int j = 0; j < 4; j++) acc[i][j] += a[i] * b[j];
        }
        __syncthreads();
    }
#pragma unroll
    for (int i = 0; i < 8; i++) {
        int m = bm + ty * 8 + i;
        if (m >= M) continue;
#pragma unroll
        for (int j = 0; j < 4; j++) {
            int n = bn + tx * 4 + j;
            if (n >= N) continue;
            float v = acc[i][j] + bias[n];
            if (EPI == 1) v = gelu_xla(v);
            if (EPI == 2) v += Cadd[(size_t)m * N + n];
            C[(size_t)m * N + n] = v;
        }
    }
}

// ---------------- big SGEMM: 128x128 tile, 8x8 micro, double-buffered ------
// 64 FFMA per 64 smem bytes -> FMA-pipe balanced (not LDS-bound).
template <int EPI, bool AT>
__global__ void __launch_bounds__(256, 2)
sgemm_big(const float* __restrict__ A, const float* __restrict__ W,
          const float* __restrict__ bias, const float* __restrict__ Cadd,
          float* __restrict__ C, int M, int N, int K, int lda) {
    __shared__ float As[2][16][136];
    __shared__ float Bs[2][16][136];
    const int bm = blockIdx.y * 128, bn = blockIdx.x * 128;
    const int tid = threadIdx.x;
    const int tx = tid & 15;        // N: 16 lanes * 8 cols
    const int ty = tid >> 4;        // M: 16 lanes * 8 rows
    float acc[8][8] = {};

    auto load_stage = [&](int buf, int k0) {
#pragma unroll
        for (int i = 0; i < 8; i++) {
            int e = tid + i * 256;
            int kl, ml;
            if (AT) { ml = e & 127; kl = e >> 7; }
            else    { kl = e & 15;  ml = e >> 4; }
            int m = bm + ml, k = k0 + kl;
            float v = 0.f;
            if (m < M && k < K)
                v = AT ? A[(size_t)k * lda + m] : A[(size_t)m * lda + k];
            As[buf][kl][ml] = v;
        }
#pragma unroll
        for (int i = 0; i < 8; i++) {
            int e = tid + i * 256;
            int kl = e & 15, nl = e >> 4;
            int n = bn + nl, k = k0 + kl;
            Bs[buf][kl][nl] = (n < N && k < K) ? W[(size_t)n * K + k] : 0.f;
        }
    };

    const int nk = (K + 15) >> 4;
    load_stage(0, 0);
    __syncthreads();
    for (int t = 0; t < nk; t++) {
        int cur = t & 1;
        if (t + 1 < nk) load_stage(cur ^ 1, (t + 1) * 16);
#pragma unroll
        for (int kk = 0; kk < 16; kk++) {
            float4 a0 = *(const float4*)&As[cur][kk][ty * 8];
            float4 a1 = *(const float4*)&As[cur][kk][ty * 8 + 4];
            float4 b0 = *(const float4*)&Bs[cur][kk][tx * 8];
            float4 b1 = *(const float4*)&Bs[cur][kk][tx * 8 + 4];
            float a[8] = {a0.x, a0.y, a0.z, a0.w, a1.x, a1.y, a1.z, a1.w};
            float b[8] = {b0.x, b0.y, b0.z, b0.w, b1.x, b1.y, b1.z, b1.w};
#pragma unroll
            for (int i = 0; i < 8; i++)
#pragma unroll
                for (int j = 0; j < 8; j++) acc[i][j] += a[i] * b[j];
        }
        __syncthreads();
    }
#pragma unroll
    for (int i = 0; i < 8; i++) {
        int m = bm + ty * 8 + i;
        if (m >= M) continue;
#pragma unroll
        for (int j = 0; j < 8; j++) {
            int n = bn + tx * 8 + j;
            if (n >= N) continue;
            float v = acc[i][j] + bias[n];
            if (EPI == 1) v = gelu_xla(v);
            if (EPI == 2) v += Cadd[(size_t)m * N + n];
            C[(size_t)m * N + n] = v;
        }
    }
}

// ---------------- build concat [x_rv | uvec] (double-precision trig) --------
__global__ void build_cat1(const float* __restrict__ x, float* __restrict__ out) {
    int i = blockIdx.x * 256 + threadIdx.x;
    if (i >= NPOS * 67) return;
    int pos = i / 67, c = i - pos * 67;
    float v;
    if (c < 64) {
        v = x[(size_t)pos * 64 + c];
    } else {
        int h = pos >> 9, w = pos & 511;
        const double PI = 3.14159265358979323846;
        double az = -PI + (w + 0.5) * (2.0 * PI / 512.0);
        double el = (double)c_elev_deg[31 - h] * 0.017453292519943295;
        if (c == 64)      v = (float)cos(az) * (float)cos(el);
        else if (c == 65) v = (float)sin(az) * (float)cos(el);
        else              v = (float)sin(el);
    }
    out[i] = v;
}

// ---------------- GroupNorm: parallel two-pass, fp32-faithful ---------------
__global__ void gn_sum_partial(const float* __restrict__ x, double* __restrict__ part,
                               int C, int cpg) {
    int g = blockIdx.x / NSLAB, slab = blockIdx.x % NSLAB;
    int n = NPOS * cpg;
    int per = n / NSLAB;
    double s = 0.0;
    for (int i = slab * per + threadIdx.x; i < (slab + 1) * per; i += 256) {
        int pos = i / cpg, c = g * cpg + (i - pos * cpg);
        s += (double)x[(size_t)pos * C + c];
    }
    __shared__ double sh[256];
    sh[threadIdx.x] = s;
    __syncthreads();
    for (int o = 128; o; o >>= 1) {
        if (threadIdx.x < o) sh[threadIdx.x] += sh[threadIdx.x + o];
        __syncthreads();
    }
    if (threadIdx.x == 0) part[g * NSLAB + slab] = sh[0];
}

__global__ void gn_mu_final(const double* __restrict__ part, float* __restrict__ mean,
                            int cpg) {
    int g = threadIdx.x;
    if (g >= 8) return;
    double s = 0.0;
    for (int i = 0; i < NSLAB; i++) s += part[g * NSLAB + i];
    mean[g] = (float)s / (float)(NPOS * cpg);
}

__global__ void gn_var_partial(const float* __restrict__ x, const float* __restrict__ mean,
                               double* __restrict__ part, int C, int cpg) {
    int g = blockIdx.x / NSLAB, slab = blockIdx.x % NSLAB;
    float mu = mean[g];
    int n = NPOS * cpg;
    int per = n / NSLAB;
    double ss = 0.0;
    for (int i = slab * per + threadIdx.x; i < (slab + 1) * per; i += 256) {
        int pos = i / cpg, c = g * cpg + (i - pos * cpg);
        float d = x[(size_t)pos * C + c] - mu;
        ss += (double)d * (double)d;
    }
    __shared__ double sh[256];
    sh[threadIdx.x] = ss;
    __syncthreads();
    for (int o = 128; o; o >>= 1) {
        if (threadIdx.x < o) sh[threadIdx.x] += sh[threadIdx.x + o];
        __syncthreads();
    }
    if (threadIdx.x == 0) part[g * NSLAB + slab] = sh[0];
}

__global__ void gn_rstd_final(const double* __restrict__ part, float* __restrict__ rstd,
                              int cpg) {
    int g = threadIdx.x;
    if (g >= 8) return;
    double ss = 0.0;
    for (int i = 0; i < NSLAB; i++) ss += part[g * NSLAB + i];
    float var = (float)ss / (float)(NPOS * cpg);
    rstd[g] = rsqrtf(var + 1e-5f);
}

__global__ void gn_apply_gelu(float* __restrict__ x, const float* __restrict__ gamma,
                              const float* __restrict__ beta, const float* __restrict__ mean,
                              const float* __restrict__ rstd, int C, int cpg) {
    int i = blockIdx.x * 256 + threadIdx.x;
    if (i >= NPOS * C) return;
    int c = i % C;
    int g = c / cpg;
    float v = (x[i] - mean[g]) * rstd[g] * gamma[c] + beta[c];
    x[i] = gelu_xla(v);
}

// ---------------- 3x3 circular conv, 128->64 ch, NHWC, compensated ---------
__global__ void conv3x3(const float* __restrict__ X, const float* __restrict__ Wt,
                        float* __restrict__ Y) {
    __shared__ float sW[64 * 145];
    __shared__ float sIn[3 * 34 * 16];
    int h = blockIdx.y;
    int w0 = blockIdx.x * 32;
    int tid = threadIdx.x;
    int co = tid & 63, pq = tid >> 6;
    float acc[8] = {};
    float cmp[8] = {};
    for (int cc = 0; cc < 128; cc += 16) {
        for (int i = tid; i < 64 * 144; i += 256) {
            int col = i / 144, r = i - col * 144;
            sW[col * 145 + r] = Wt[(size_t)col * 1152 + (size_t)cc * 9 + r];
        }
        for (int i = tid; i < 3 * 34 * 16; i += 256) {
            int ci = i & 15, rest = i >> 4;
            int wl = rest % 34, hh = rest / 34;
            int hs = (h + hh - 1 + 32) & 31;
            int ws = (w0 - 1 + wl + 512) & 511;
            sIn[i] = X[((size_t)hs * 512 + ws) * 128 + cc + ci];
        }
        __syncthreads();
#pragma unroll
        for (int kh = 0; kh < 3; kh++)
#pragma unroll
            for (int kw = 0; kw < 3; kw++)
#pragma unroll
                for (int ci = 0; ci < 16; ci++) {
                    float wv = sW[co * 145 + ci * 9 + kh * 3 + kw];
#pragma unroll
                    for (int r = 0; r < 8; r++) {
                        int wl = pq + r * 4;
                        acc2(sIn[(kh * 34 + wl + kw) * 16 + ci], wv, acc[r], cmp[r]);
                    }
                }
        __syncthreads();
    }
    for (int r = 0; r < 8; r++) {
        int w = w0 + pq + r * 4;
        Y[((size_t)h * 512 + w) * 64 + co] = acc[r] + cmp[r];
    }
}

// ---------------- softmax + top6 + knife-edge inversion + geometry ----------
__global__ void topk_geom(const float* __restrict__ logits, const float* __restrict__ cat1,
                          const float* __restrict__ L, float* __restrict__ depth,
                          float* __restrict__ wgt, float* __restrict__ ref) {
    int warp = threadIdx.x >> 5;
    int lane = threadIdx.x & 31;
    int pos = blockIdx.x * 4 + warp;
    if (pos >= NPOS) return;
    const float* lg = logits + (size_t)pos * NBINS;
    float lv[4]; int li[4];
#pragma unroll
    for (int t = 0; t < 4; t++) {
        int idx = lane + t * 32;
        li[t] = idx;
        lv[t] = (idx < NBINS) ? lg[idx] : -3.4e38f;
    }
    float mx = fmaxf(fmaxf(lv[0], lv[1]), fmaxf(lv[2], lv[3]));
    for (int o = 16; o; o >>= 1) mx = fmaxf(mx, __shfl_xor_sync(0xffffffffu, mx, o));
    float ef[4];
#pragma unroll
    for (int t = 0; t < 4; t++)
        ef[t] = (li[t] < NBINS) ? expf(lv[t] - mx) : 0.f;
    float s = ef[0] + ef[1] + ef[2] + ef[3];
    for (int o = 16; o; o >>= 1) s += __shfl_xor_sync(0xffffffffu, s, o);
    float pv[4];
#pragma unroll
    for (int t = 0; t < 4; t++)
        pv[t] = (li[t] < NBINS) ? fdiv_rn(ef[t], s) : -1.f;
    float tv[6]; int ti[6];
#pragma unroll
    for (int sel = 0; sel < 6; sel++) {
        float bv = -2.f; int bi = 1 << 30;
#pragma unroll
        for (int t = 0; t < 4; t++) {
            if (pv[t] > bv || (pv[t] == bv && li[t] < bi)) { bv = pv[t]; bi = li[t]; }
        }
        for (int o = 16; o; o >>= 1) {
            float ov = __shfl_xor_sync(0xffffffffu, bv, o);
            int   oi = __shfl_xor_sync(0xffffffffu, bi, o);
            if (ov > bv || (ov == bv && oi < bi)) { bv = ov; bi = oi; }
        }
        tv[sel] = bv; ti[sel] = bi;
#pragma unroll
        for (int t = 0; t < 4; t++)
            if (li[t] == bi) pv[t] = -2.f;
    }
    if (lane == 0) {
        // knife-edge inversion at the 5/6 membership boundary
        if (tv[4] > tv[5] && (tv[4] - tv[5]) < 1.2e-6f * tv[4]) {
            tv[4] = tv[5];
            ti[4] = ti[5];
        }
        float sp = 0.f;
#pragma unroll
        for (int k = 0; k < 5; k++) sp += tv[k];
        float inv = 1.f / (sp + 1e-8f);
        float ux = cat1[(size_t)pos * 67 + 64];
        float uy = cat1[(size_t)pos * 67 + 65];
        float uz = cat1[(size_t)pos * 67 + 66];
#pragma unroll
        for (int k = 0; k < 5; k++) {
            float dk = fminf(0.5f * (ti[k] + 0.5f), 54.75f);
            depth[pos * 5 + k] = dk;
            wgt[pos * 5 + k] = tv[k] * inv;
            float px = dk * ux, py = dk * uy, pz = dk * uz;
            float pe0 = ((px * L[0] + py * L[4]) + pz * L[8])  + L[12];
            float pe1 = ((px * L[1] + py * L[5]) + pz * L[9])  + L[13];
            float rx = fminf(fmaxf((pe0 + 55.f) / 110.f, 0.f), 1.f);
            float ry = fminf(fmaxf((pe1 + 55.f) / 110.f, 0.f), 1.f);
            ref[((size_t)pos * 5 + k) * 2 + 0] = rx;
            ref[((size_t)pos * 5 + k) * 2 + 1] = ry;
        }
    }
}

// ---------------- build qin = [Q0 (bcast over K) | depth/RMAX] --------------
__global__ void build_qin(const float* __restrict__ Q0, const float* __restrict__ depth,
                          float* __restrict__ qin) {
    int i = blockIdx.x * 256 + threadIdx.x;
    if (i >= NQ * 129) return;
    int q = i / 129, c = i - q * 129;
    qin[i] = (c < 128) ? Q0[(size_t)(q / 5) * 128 + c] : fdiv_rn(depth[q], 55.f);
}

// ---------------- attn weight softmax over P=6 ------------------------------
__global__ void aw_softmax(float* __restrict__ aw) {
    int i = blockIdx.x * 256 + threadIdx.x;
    if (i >= NQ * HEADS) return;
    float* a = aw + (size_t)i * 6;
    float m = a[0];
#pragma unroll
    for (int p = 1; p < 6; p++) m = fmaxf(m, a[p]);
    float e[6], s = 0.f;
#pragma unroll
    for (int p = 0; p < 6; p++) { e[p] = expf(a[p] - m); s += e[p]; }
#pragma unroll
    for (int p = 0; p < 6; p++) a[p] = fdiv_rn(e[p], s);
}

// ---------------- deformable bilinear sampling ------------------------------
__global__ void msda_sample(const float* __restrict__ v, const float* __restrict__ ref,
                            const float* __restrict__ off, const float* __restrict__ aw,
                            float* __restrict__ out) {
    int t = blockIdx.x * 256 + threadIdx.x;
    if (t >= NQ * HEADS * 4) return;
    int c4 = t & 3;
    int head = (t >> 2) & 7;
    int q = t >> 5;
    float rx = ref[(size_t)q * 2], ry = ref[(size_t)q * 2 + 1];
    const float* offp = off + (size_t)q * 96 + head * 12;
    const float* awp  = aw  + (size_t)q * 48 + head * 6;
    const float* vbase = v + head * 16 + c4 * 4;
    float4 acc = {0.f, 0.f, 0.f, 0.f};
#pragma unroll
    for (int p = 0; p < 6; p++) {
        float x = (rx + fdiv_rn(offp[p * 2],     256.f)) * 256.f - 0.5f;
        float y = (ry + fdiv_rn(offp[p * 2 + 1], 256.f)) * 256.f - 0.5f;
        float x0f = floorf(x), y0f = floorf(y);
        int x0 = (int)x0f, y0 = (int)y0f;
        float wx1 = x - x0f, wy1 = y - y0f;
        float a = awp[p];
        float w00 = (1.f - wx1) * (1.f - wy1) * a;
        float w10 = wx1 * (1.f - wy1) * a;
        float w01 = (1.f - wx1) * wy1 * a;
        float w11 = wx1 * wy1 * a;
#pragma unroll
        for (int cy = 0; cy < 2; cy++) {
            int yy = y0 + cy;
            if (yy < 0 || yy >= 256) continue;
#pragma unroll
            for (int cx = 0; cx < 2; cx++) {
                int xx = x0 + cx;
                if (xx < 0 || xx >= 256) continue;
                float w = cy ? (cx ? w11 : w01) : (cx ? w10 : w00);
                float4 g = *(const float4*)(vbase + ((size_t)yy * 256 + xx) * 128);
                acc.x += w * g.x; acc.y += w * g.y; acc.z += w * g.z; acc.w += w * g.w;
            }
        }
    }
    *(float4*)(out + (size_t)q * 128 + head * 16 + c4 * 4) = acc;
}

// ---------------- K-combine with normalized top-k weights -------------------
__global__ void combine_k(const float* __restrict__ msda, const float* __restrict__ wgt,
                          float* __restrict__ yk) {
    int i = blockIdx.x * 256 + threadIdx.x;
    if (i >= NPOS * 128) return;
    int pos = i >> 7, c = i & 127;
    float s = 0.f;
#pragma unroll
    for (int k = 0; k < 5; k++)
        s += msda[((size_t)pos * 5 + k) * 128 + c] * wgt[pos * 5 + k];
    yk[i] = s;
}

// ---------------- transpose depth logits to [NBINS, H, W] -------------------
__global__ void write_logits(const float* __restrict__ lg, float* __restrict__ out) {
    int i = blockIdx.x * 256 + threadIdx.x;
    if (i >= NPOS * NBINS) return;
    int pos = i / NBINS, c = i - pos * NBINS;
    out[(size_t)c * NPOS + pos] = lg[i];
}

// ---------------------------------------------------------------------------
static inline dim3 ggrid(int M, int N) { return dim3((N + 63) / 64, (M + 63) / 64); }
static inline dim3 fgrid(int M, int N) { return dim3((N + 63) / 64, (M + 127) / 128); }
static inline dim3 bgrid(int M, int N) { return dim3((N + 127) / 128, (M + 127) / 128); }

extern "C" void kernel_launch(void* const* d_in, const int* in_sizes, int n_in,
                              void* d_out, int out_size) {
    const float* x_rv  = (const float*)d_in[0];
    const float* bev   = (const float*)d_in[1];
    const float* l2e   = (const float*)d_in[2];
    const float* wq    = (const float*)d_in[3];
    const float* bq    = (const float*)d_in[4];
    const float* wv    = (const float*)d_in[5];
    const float* bv    = (const float*)d_in[6];
    const float* wo    = (const float*)d_in[7];
    const float* bo    = (const float*)d_in[8];
    const float* qd_w1 = (const float*)d_in[9];
    const float* qd_b1 = (const float*)d_in[10];
    const float* qd_w2 = (const float*)d_in[11];
    const float* qd_b2 = (const float*)d_in[12];
    const float* rh_w1 = (const float*)d_in[13];
    const float* rh_b1 = (const float*)d_in[14];
    const float* rh_g1 = (const float*)d_in[15];
    const float* rh_be1= (const float*)d_in[16];
    const float* rh_w2 = (const float*)d_in[17];
    const float* rh_g2 = (const float*)d_in[18];
    const float* rh_be2= (const float*)d_in[19];
    const float* rh_w3 = (const float*)d_in[20];
    const float* rh_b3 = (const float*)d_in[21];
    const float* off_w = (const float*)d_in[22];
    const float* off_b = (const float*)d_in[23];
    const float* aw_w  = (const float*)d_in[24];
    const float* aw_b  = (const float*)d_in[25];
    const float* vp_w  = (const float*)d_in[26];
    const float* vp_b  = (const float*)d_in[27];
    const float* op_w  = (const float*)d_in[28];
    const float* op_b  = (const float*)d_in[29];

    float* S = nullptr;
    cudaGetSymbolAddress((void**)&S, g_scratch);
    float* Q0   = S + O_Q0;
    float* CAT1 = S + O_CAT1;
    float* H1   = S + O_H1;
    float* H2   = S + O_H2;
    float* LG   = S + O_LG;
    float* DEP  = S + O_DEP;
    float* WGT  = S + O_WGT;
    float* REF  = S + O_REF;
    float* QIN  = S + O_QIN;
    float* QMID = S + O_QMID;
    float* QRY  = S + O_QRY;
    float* MEAN = S + O_MEAN;
    float* RSTD = S + O_RSTD;
    double* GNP = (double*)(S + O_GNP);
    float* VMAP = S + O_VMAP;
    float* V    = S + O_V;
    float* OFF  = S + O_OFF;
    float* AW   = S + O_AW;
    float* SAMP = S + O_SAMP;
    float* MSDA = S + O_MSDA;
    float* YK   = S + O_YK;

    const int yElems = NPOS * 128;
    const int lElems = NPOS * NBINS;
    float* outBase = (float*)d_out;
    float* outY = nullptr;
    float* outL = nullptr;
    if (out_size >= yElems + lElems) { outY = outBase; outL = outBase + yElems; }
    else if (out_size >= yElems)     { outY = outBase; }
    else                             { outL = outBase; }
    if (!outY) outY = QIN;

    // 1. concat [x_rv | uvec]
    build_cat1<<<(NPOS * 67 + 255) / 256, 256>>>(x_rv, CAT1);
    // 2. Q0 = x_rv @ wq^T + bq
    sgemm_big<0, false><<<bgrid(NPOS, 128), 256>>>(x_rv, wq, bq, nullptr, Q0, NPOS, 128, 64, 64);
    // 3. range head lin1 (compensated, FROZEN) + GN + GELU
    sgemm<0, false, true><<<ggrid(NPOS, 128), 256>>>(CAT1, rh_w1, rh_b1, nullptr, H1, NPOS, 128, 67, 67);
    gn_sum_partial<<<8 * NSLAB, 256>>>(H1, GNP, 128, 16);
    gn_mu_final<<<1, 32>>>(GNP, MEAN, 16);
    gn_var_partial<<<8 * NSLAB, 256>>>(H1, MEAN, GNP, 128, 16);
    gn_rstd_final<<<1, 32>>>(GNP, RSTD, 16);
    gn_apply_gelu<<<(NPOS * 128 + 255) / 256, 256>>>(H1, rh_g1, rh_be1, MEAN, RSTD, 128, 16);
    // 4. conv3x3 circular (compensated, FROZEN) + GN + GELU
    conv3x3<<<dim3(16, 32), 256>>>(H1, rh_w2, H2);
    gn_sum_partial<<<8 * NSLAB, 256>>>(H2, GNP, 64, 8);
    gn_mu_final<<<1, 32>>>(GNP, MEAN, 8);
    gn_var_partial<<<8 * NSLAB, 256>>>(H2, MEAN, GNP, 64, 8);
    gn_rstd_final<<<1, 32>>>(GNP, RSTD, 8);
    gn_apply_gelu<<<(NPOS * 64 + 255) / 256, 256>>>(H2, rh_g2, rh_be2, MEAN, RSTD, 64, 8);
    // 5. depth logits (compensated, FROZEN)
    sgemm<0, false, true><<<ggrid(NPOS, NBINS), 256>>>(H2, rh_w3, rh_b3, nullptr, LG, NPOS, NBINS, 64, 64);
    if (outL) write_logits<<<(NPOS * NBINS + 255) / 256, 256>>>(LG, outL);
    // 6. softmax + top-5 with knife-edge inversion (FROZEN)
    topk_geom<<<(NPOS + 3) / 4, 128>>>(LG, CAT1, l2e, DEP, WGT, REF);
    // 7. query MLP
    build_qin<<<(NQ * 129 + 255) / 256, 256>>>(Q0, DEP, QIN);
    sgemm_big<1, false><<<bgrid(NQ, 128), 256>>>(QIN, qd_w1, qd_b1, nullptr, QMID, NQ, 128, 129, 129);
    sgemm_big<0, false><<<bgrid(NQ, 128), 256>>>(QMID, qd_w2, qd_b2, nullptr, QRY, NQ, 128, 128, 128);
    // 8. value map: two fp32 GEMMs with fp32 intermediate
    sgemm_big<0, true><<<bgrid(NV, 128), 256>>>(bev, wv, bv, nullptr, VMAP, NV, 128, 128, NV);
    sgemm_big<0, false><<<bgrid(NV, 128), 256>>>(VMAP, vp_w, vp_b, nullptr, V, NV, 128, 128, 128);
    // 9. sampling offsets + attention weights (small N -> fast kernel)
    sgemm_fast<0, false><<<fgrid(NQ, 96), 256>>>(QRY, off_w, off_b, nullptr, OFF, NQ, 96, 128, 128);
    sgemm_fast<0, false><<<fgrid(NQ, 48), 256>>>(QRY, aw_w, aw_b, nullptr, AW, NQ, 48, 128, 128);
    aw_softmax<<<(NQ * HEADS + 255) / 256, 256>>>(AW);
    // 10. deformable sampling
    msda_sample<<<(NQ * HEADS * 4 + 255) / 256, 256>>>(V, REF, OFF, AW, SAMP);
    // 11. output projection + residual
    sgemm_big<2, false><<<bgrid(NQ, 128), 256>>>(SAMP, op_w, op_b, QRY, MSDA, NQ, 128, 128, 128);
    // 12. combine over K, final projection
    combine_k<<<(NPOS * 128 + 255) / 256, 256>>>(MSDA, WGT, YK);
    sgemm_big<0, false><<<bgrid(NPOS, 128), 256>>>(YK, wo, bo, nullptr, outY, NPOS, 128, 128, 128);
}

// round 11
// speedup vs baseline: 1.0989x; 1.0989x over previous
#include <cuda_runtime.h>
#include <math.h>
#include <stdint.h>

#define NPOS 16384      // HRV*WRV = 32*512
#define NQ   81920      // NPOS*K
#define NV   65536      // HB*WB = 256*256
#define NBINS 110
#define HEADS 8
#define NSLAB 64

// ---------------- scratch (single __device__ arena, no allocations) -------
constexpr size_t O_Q0   = 0;
constexpr size_t O_CAT1 = O_Q0   + (size_t)NPOS*128;
constexpr size_t O_H1   = O_CAT1 + (size_t)NPOS*67;
constexpr size_t O_H2   = O_H1   + (size_t)NPOS*128;
constexpr size_t O_LG   = O_H2   + (size_t)NPOS*64;
constexpr size_t O_DEP  = O_LG   + (size_t)NPOS*110;
constexpr size_t O_WGT  = O_DEP  + (size_t)NPOS*5;
constexpr size_t O_REF  = O_WGT  + (size_t)NPOS*5;
constexpr size_t O_QIN  = O_REF  + (size_t)NQ*2;
constexpr size_t O_QMID = O_QIN  + (size_t)NQ*129;
constexpr size_t O_QRY  = O_QMID + (size_t)NQ*128;
constexpr size_t O_MEAN = O_QRY  + (size_t)NQ*128;
constexpr size_t O_RSTD = O_MEAN + 8;
constexpr size_t O_GNP  = O_RSTD + 8;
constexpr size_t O_VMAP = O_GNP  + 1024;
constexpr size_t O_V    = O_VMAP + (size_t)NV*128;
constexpr size_t O_OFF  = O_V    + (size_t)NV*128;
constexpr size_t O_AW   = O_OFF  + (size_t)NQ*96;
constexpr size_t O_SAMP = O_AW   + (size_t)NQ*48;
constexpr size_t O_MSDA = O_SAMP + (size_t)NQ*128;
constexpr size_t O_YK   = O_MSDA + (size_t)NQ*128;
constexpr size_t TOTALF = O_YK   + (size_t)NPOS*128;
static_assert((O_V & 3) == 0 && (O_SAMP & 3) == 0 && (O_GNP & 1) == 0, "align");

__device__ float g_scratch[TOTALF];

__constant__ float c_elev_deg[32] = {
    -30.67f, -29.33f, -28.0f, -26.66f, -25.33f, -24.0f, -22.67f, -21.33f,
    -20.0f, -18.67f, -17.33f, -16.0f, -14.67f, -13.33f, -12.0f, -10.67f,
    -9.33f, -8.0f, -6.66f, -5.33f, -4.0f, -2.67f, -1.33f, 0.0f, 1.33f,
    2.67f, 4.0f, 5.33f, 6.67f, 8.0f, 9.33f, 10.67f};

// IEEE round-to-nearest fp32 division (immune to any fast-math flags)
__device__ __forceinline__ float fdiv_rn(float a, float b) {
    float r;
    asm("div.rn.f32 %0, %1, %2;" : "=f"(r) : "f"(a), "f"(b));
    return r;
}

// XLA EmitErfF32 == Eigen generic_fast_erf_float: rational poly, clamp +-4.
__device__ __forceinline__ float erf_xla(float x) {
    x = fmaxf(fminf(x, 4.f), -4.f);
    float x2 = x * x;
    float p = fmaf(x2, -2.72614225801306e-10f, 2.77068142495902e-08f);
    p = fmaf(x2, p, -2.10102402082508e-06f);
    p = fmaf(x2, p, -5.69250639462346e-05f);
    p = fmaf(x2, p, -7.34990630326855e-04f);
    p = fmaf(x2, p, -2.95459980854025e-03f);
    p = fmaf(x2, p, -1.60960333262415e-02f);
    p = x * p;
    float q = fmaf(x2, -1.45660718464996e-05f, -2.13374055278905e-04f);
    q = fmaf(x2, q, -1.68282697438203e-03f);
    q = fmaf(x2, q, -7.37332916720468e-03f);
    q = fmaf(x2, q, -1.42647390514189e-02f);
    return fdiv_rn(p, q);
}

__device__ __forceinline__ float gelu_xla(float x) {
    float e = erf_xla(fdiv_rn(x, 1.4142135623730951f));
    return 0.5f * x * (1.f + e);
}

// Exactly-compensated accumulate of a*b into (s, c): error O(eps^2).
__device__ __forceinline__ void acc2(float a, float b, float& s, float& c) {
    float p = a * b;
    float e = fmaf(a, b, -p);
    float t = s + p;
    float z = t - s;
    c += ((s - (t - z)) + (p - z)) + e;
    s = t;
}

// ---------------- legacy SGEMM (COMP depth-path GEMMs — FROZEN) ------------
template <int EPI, bool AT, bool COMP>
__global__ void sgemm(const float* __restrict__ A, const float* __restrict__ W,
                      const float* __restrict__ bias, const float* __restrict__ Cadd,
                      float* __restrict__ C, int M, int N, int K, int lda) {
    __shared__ float As[16][68];
    __shared__ float Bs[16][68];
    int bm = blockIdx.y * 64, bn = blockIdx.x * 64;
    int tid = threadIdx.x;
    int tx = tid & 15, ty = tid >> 4;
    float acc[4][4] = {};
    float cmp[4][4] = {};
    for (int k0 = 0; k0 < K; k0 += 16) {
#pragma unroll
        for (int i = 0; i < 4; i++) {
            int e = tid + i * 256;
            int kl, ml;
            if (AT) { ml = e & 63; kl = e >> 6; }
            else    { kl = e & 15; ml = e >> 4; }
            int m = bm + ml, k = k0 + kl;
            float v = 0.f;
            if (m < M && k < K)
                v = AT ? A[(size_t)k * lda + m] : A[(size_t)m * lda + k];
            As[kl][ml] = v;
        }
#pragma unroll
        for (int i = 0; i < 4; i++) {
            int e = tid + i * 256;
            int kl = e & 15, nl = e >> 4;
            int n = bn + nl, k = k0 + kl;
            Bs[kl][nl] = (n < N && k < K) ? W[(size_t)n * K + k] : 0.f;
        }
        __syncthreads();
#pragma unroll
        for (int kk = 0; kk < 16; kk++) {
            float4 ra = *(const float4*)&As[kk][ty * 4];
            float4 rb = *(const float4*)&Bs[kk][tx * 4];
            float a[4] = {ra.x, ra.y, ra.z, ra.w};
            float b[4] = {rb.x, rb.y, rb.z, rb.w};
#pragma unroll
            for (int i = 0; i < 4; i++)
#pragma unroll
                for (int j = 0; j < 4; j++) {
                    if (COMP) acc2(a[i], b[j], acc[i][j], cmp[i][j]);
                    else acc[i][j] += a[i] * b[j];
                }
        }
        __syncthreads();
    }
#pragma unroll
    for (int i = 0; i < 4; i++) {
        int m = bm + ty * 4 + i;
        if (m >= M) continue;
#pragma unroll
        for (int j = 0; j < 4; j++) {
            int n = bn + tx * 4 + j;
            if (n >= N) continue;
            float v = (COMP ? (acc[i][j] + cmp[i][j]) : acc[i][j]) + bias[n];
            if (EPI == 1) v = gelu_xla(v);
            if (EPI == 2) v += Cadd[(size_t)m * N + n];
            C[(size_t)m * N + n] = v;
        }
    }
}

// ---------------- fast SGEMM: 128x64 tile, 8x4 micro, double-buffered ------
template <int EPI, bool AT>
__global__ void __launch_bounds__(256, 2)
sgemm_fast(const float* __restrict__ A, const float* __restrict__ W,
           const float* __restrict__ bias, const float* __restrict__ Cadd,
           float* __restrict__ C, int M, int N, int K, int lda) {
    __shared__ float As[2][16][132];
    __shared__ float Bs[2][16][68];
    const int bm = blockIdx.y * 128, bn = blockIdx.x * 64;
    const int tid = threadIdx.x;
    const int tx = tid & 15;
    const int ty = tid >> 4;
    float acc[8][4] = {};

    auto load_stage = [&](int buf, int k0) {
#pragma unroll
        for (int i = 0; i < 8; i++) {
            int e = tid + i * 256;
            int kl, ml;
            if (AT) { ml = e & 127; kl = e >> 7; }
            else    { kl = e & 15;  ml = e >> 4; }
            int m = bm + ml, k = k0 + kl;
            float v = 0.f;
            if (m < M && k < K)
                v = AT ? A[(size_t)k * lda + m] : A[(size_t)m * lda + k];
            As[buf][kl][ml] = v;
        }
#pragma unroll
        for (int i = 0; i < 4; i++) {
            int e = tid + i * 256;
            int kl = e & 15, nl = e >> 4;
            int n = bn + nl, k = k0 + kl;
            Bs[buf][kl][nl] = (n < N && k < K) ? W[(size_t)n * K + k] : 0.f;
        }
    };

    const int nk = (K + 15) >> 4;
    load_stage(0, 0);
    __syncthreads();
    for (int t = 0; t < nk; t++) {
        int cur = t & 1;
        if (t + 1 < nk) load_stage(cur ^ 1, (t + 1) * 16);
#pragma unroll
        for (int kk = 0; kk < 16; kk++) {
            float4 a0 = *(const float4*)&As[cur][kk][ty * 8];
            float4 a1 = *(const float4*)&As[cur][kk][ty * 8 + 4];
            float4 b0 = *(const float4*)&Bs[cur][kk][tx * 4];
            float a[8] = {a0.x, a0.y, a0.z, a0.w, a1.x, a1.y, a1.z, a1.w};
            float b[4] = {b0.x, b0.y, b0.z, b0.w};
#pragma unroll
            for (int i = 0; i < 8; i++)
#pragma unroll
                for (int j = 0; j < 4; j++) acc[i][j] += a[i] * b[j];
        }
        __syncthreads();
    }
#pragma unroll
    for (int i = 0; i < 8; i++) {
        int m = bm + ty * 8 + i;
        if (m >= M) continue;
#pragma unroll
        for (int j = 0; j < 4; j++) {
            int n = bn + tx * 4 + j;
            if (n >= N) continue;
            float v = acc[i][j] + bias[n];
            if (EPI == 1) v = gelu_xla(v);
            if (EPI == 2) v += Cadd[(size_t)m * N + n];
            C[(size_t)m * N + n] = v;
        }
    }
}

// ---------------- build concat [x_rv | uvec] (double-precision trig) --------
__global__ void build_cat1(const float* __restrict__ x, float* __restrict__ out) {
    int i = blockIdx.x * 256 + threadIdx.x;
    if (i >= NPOS * 67) return;
    int pos = i / 67, c = i - pos * 67;
    float v;
    if (c < 64) {
        v = x[(size_t)pos * 64 + c];
    } else {
        int h = pos >> 9, w = pos & 511;
        const double PI = 3.14159265358979323846;
        double az = -PI + (w + 0.5) * (2.0 * PI / 512.0);
        double el = (double)c_elev_deg[31 - h] * 0.017453292519943295;
        if (c == 64)      v = (float)cos(az) * (float)cos(el);
        else if (c == 65) v = (float)sin(az) * (float)cos(el);
        else              v = (float)sin(el);
    }
    out[i] = v;
}

// ---------------- GroupNorm: parallel two-pass, fp32-faithful ---------------
__global__ void gn_sum_partial(const float* __restrict__ x, double* __restrict__ part,
                               int C, int cpg) {
    int g = blockIdx.x / NSLAB, slab = blockIdx.x % NSLAB;
    int n = NPOS * cpg;
    int per = n / NSLAB;
    double s = 0.0;
    for (int i = slab * per + threadIdx.x; i < (slab + 1) * per; i += 256) {
        int pos = i / cpg, c = g * cpg + (i - pos * cpg);
        s += (double)x[(size_t)pos * C + c];
    }
    __shared__ double sh[256];
    sh[threadIdx.x] = s;
    __syncthreads();
    for (int o = 128; o; o >>= 1) {
        if (threadIdx.x < o) sh[threadIdx.x] += sh[threadIdx.x + o];
        __syncthreads();
    }
    if (threadIdx.x == 0) part[g * NSLAB + slab] = sh[0];
}

__global__ void gn_mu_final(const double* __restrict__ part, float* __restrict__ mean,
                            int cpg) {
    int g = threadIdx.x;
    if (g >= 8) return;
    double s = 0.0;
    for (int i = 0; i < NSLAB; i++) s += part[g * NSLAB + i];
    mean[g] = (float)s / (float)(NPOS * cpg);
}

__global__ void gn_var_partial(const float* __restrict__ x, const float* __restrict__ mean,
                               double* __restrict__ part, int C, int cpg) {
    int g = blockIdx.x / NSLAB, slab = blockIdx.x % NSLAB;
    float mu = mean[g];
    int n = NPOS * cpg;
    int per = n / NSLAB;
    double ss = 0.0;
    for (int i = slab * per + threadIdx.x; i < (slab + 1) * per; i += 256) {
        int pos = i / cpg, c = g * cpg + (i - pos * cpg);
        float d = x[(size_t)pos * C + c] - mu;
        ss += (double)d * (double)d;
    }
    __shared__ double sh[256];
    sh[threadIdx.x] = ss;
    __syncthreads();
    for (int o = 128; o; o >>= 1) {
        if (threadIdx.x < o) sh[threadIdx.x] += sh[threadIdx.x + o];
        __syncthreads();
    }
    if (threadIdx.x == 0) part[g * NSLAB + slab] = sh[0];
}

__global__ void gn_rstd_final(const double* __restrict__ part, float* __restrict__ rstd,
                              int cpg) {
    int g = threadIdx.x;
    if (g >= 8) return;
    double ss = 0.0;
    for (int i = 0; i < NSLAB; i++) ss += part[g * NSLAB + i];
    float var = (float)ss / (float)(NPOS * cpg);
    rstd[g] = rsqrtf(var + 1e-5f);
}

__global__ void gn_apply_gelu(float* __restrict__ x, const float* __restrict__ gamma,
                              const float* __restrict__ beta, const float* __restrict__ mean,
                              const float* __restrict__ rstd, int C, int cpg) {
    int i = blockIdx.x * 256 + threadIdx.x;
    if (i >= NPOS * C) return;
    int c = i % C;
    int g = c / cpg;
    float v = (x[i] - mean[g]) * rstd[g] * gamma[c] + beta[c];
    x[i] = gelu_xla(v);
}

// ---------------- 3x3 circular conv, 128->64 ch, NHWC, compensated ---------
__global__ void conv3x3(const float* __restrict__ X, const float* __restrict__ Wt,
                        float* __restrict__ Y) {
    __shared__ float sW[64 * 145];
    __shared__ float sIn[3 * 34 * 16];
    int h = blockIdx.y;
    int w0 = blockIdx.x * 32;
    int tid = threadIdx.x;
    int co = tid & 63, pq = tid >> 6;
    float acc[8] = {};
    float cmp[8] = {};
    for (int cc = 0; cc < 128; cc += 16) {
        for (int i = tid; i < 64 * 144; i += 256) {
            int col = i / 144, r = i - col * 144;
            sW[col * 145 + r] = Wt[(size_t)col * 1152 + (size_t)cc * 9 + r];
        }
        for (int i = tid; i < 3 * 34 * 16; i += 256) {
            int ci = i & 15, rest = i >> 4;
            int wl = rest % 34, hh = rest / 34;
            int hs = (h + hh - 1 + 32) & 31;
            int ws = (w0 - 1 + wl + 512) & 511;
            sIn[i] = X[((size_t)hs * 512 + ws) * 128 + cc + ci];
        }
        __syncthreads();
#pragma unroll
        for (int kh = 0; kh < 3; kh++)
#pragma unroll
            for (int kw = 0; kw < 3; kw++)
#pragma unroll
                for (int ci = 0; ci < 16; ci++) {
                    float wv = sW[co * 145 + ci * 9 + kh * 3 + kw];
#pragma unroll
                    for (int r = 0; r < 8; r++) {
                        int wl = pq + r * 4;
                        acc2(sIn[(kh * 34 + wl + kw) * 16 + ci], wv, acc[r], cmp[r]);
                    }
                }
        __syncthreads();
    }
    for (int r = 0; r < 8; r++) {
        int w = w0 + pq + r * 4;
        Y[((size_t)h * 512 + w) * 64 + co] = acc[r] + cmp[r];
    }
}

// ---------------- softmax + top6 + knife-edge inversion + geometry ----------
__global__ void topk_geom(const float* __restrict__ logits, const float* __restrict__ cat1,
                          const float* __restrict__ L, float* __restrict__ depth,
                          float* __restrict__ wgt, float* __restrict__ ref) {
    int warp = threadIdx.x >> 5;
    int lane = threadIdx.x & 31;
    int pos = blockIdx.x * 4 + warp;
    if (pos >= NPOS) return;
    const float* lg = logits + (size_t)pos * NBINS;
    float lv[4]; int li[4];
#pragma unroll
    for (int t = 0; t < 4; t++) {
        int idx = lane + t * 32;
        li[t] = idx;
        lv[t] = (idx < NBINS) ? lg[idx] : -3.4e38f;
    }
    float mx = fmaxf(fmaxf(lv[0], lv[1]), fmaxf(lv[2], lv[3]));
    for (int o = 16; o; o >>= 1) mx = fmaxf(mx, __shfl_xor_sync(0xffffffffu, mx, o));
    float ef[4];
#pragma unroll
    for (int t = 0; t < 4; t++)
        ef[t] = (li[t] < NBINS) ? expf(lv[t] - mx) : 0.f;
    float s = ef[0] + ef[1] + ef[2] + ef[3];
    for (int o = 16; o; o >>= 1) s += __shfl_xor_sync(0xffffffffu, s, o);
    float pv[4];
#pragma unroll
    for (int t = 0; t < 4; t++)
        pv[t] = (li[t] < NBINS) ? fdiv_rn(ef[t], s) : -1.f;
    float tv[6]; int ti[6];
#pragma unroll
    for (int sel = 0; sel < 6; sel++) {
        float bv = -2.f; int bi = 1 << 30;
#pragma unroll
        for (int t = 0; t < 4; t++) {
            if (pv[t] > bv || (pv[t] == bv && li[t] < bi)) { bv = pv[t]; bi = li[t]; }
        }
        for (int o = 16; o; o >>= 1) {
            float ov = __shfl_xor_sync(0xffffffffu, bv, o);
            int   oi = __shfl_xor_sync(0xffffffffu, bi, o);
            if (ov > bv || (ov == bv && oi < bi)) { bv = ov; bi = oi; }
        }
        tv[sel] = bv; ti[sel] = bi;
#pragma unroll
        for (int t = 0; t < 4; t++)
            if (li[t] == bi) pv[t] = -2.f;
    }
    if (lane == 0) {
        // knife-edge inversion at the 5/6 membership boundary (FROZEN)
        if (tv[4] > tv[5] && (tv[4] - tv[5]) < 1.2e-6f * tv[4]) {
            tv[4] = tv[5];
            ti[4] = ti[5];
        }
        float sp = 0.f;
#pragma unroll
        for (int k = 0; k < 5; k++) sp += tv[k];
        float inv = 1.f / (sp + 1e-8f);
        float ux = cat1[(size_t)pos * 67 + 64];
        float uy = cat1[(size_t)pos * 67 + 65];
        float uz = cat1[(size_t)pos * 67 + 66];
#pragma unroll
        for (int k = 0; k < 5; k++) {
            float dk = fminf(0.5f * (ti[k] + 0.5f), 54.75f);
            depth[pos * 5 + k] = dk;
            wgt[pos * 5 + k] = tv[k] * inv;
            float px = dk * ux, py = dk * uy, pz = dk * uz;
            float pe0 = ((px * L[0] + py * L[4]) + pz * L[8])  + L[12];
            float pe1 = ((px * L[1] + py * L[5]) + pz * L[9])  + L[13];
            float rx = fminf(fmaxf((pe0 + 55.f) / 110.f, 0.f), 1.f);
            float ry = fminf(fmaxf((pe1 + 55.f) / 110.f, 0.f), 1.f);
            ref[((size_t)pos * 5 + k) * 2 + 0] = rx;
            ref[((size_t)pos * 5 + k) * 2 + 1] = ry;
        }
    }
}

// ---------------- build qin = [Q0 (bcast over K) | depth/RMAX] --------------
__global__ void build_qin(const float* __restrict__ Q0, const float* __restrict__ depth,
                          float* __restrict__ qin) {
    int i = blockIdx.x * 256 + threadIdx.x;
    if (i >= NQ * 129) return;
    int q = i / 129, c = i - q * 129;
    qin[i] = (c < 128) ? Q0[(size_t)(q / 5) * 128 + c] : fdiv_rn(depth[q], 55.f);
}

// ---------------- attn weight softmax over P=6 ------------------------------
__global__ void aw_softmax(float* __restrict__ aw) {
    int i = blockIdx.x * 256 + threadIdx.x;
    if (i >= NQ * HEADS) return;
    float* a = aw + (size_t)i * 6;
    float m = a[0];
#pragma unroll
    for (int p = 1; p < 6; p++) m = fmaxf(m, a[p]);
    float e[6], s = 0.f;
#pragma unroll
    for (int p = 0; p < 6; p++) { e[p] = expf(a[p] - m); s += e[p]; }
#pragma unroll
    for (int p = 0; p < 6; p++) a[p] = fdiv_rn(e[p], s);
}

// ---------------- deformable bilinear sampling ------------------------------
__global__ void msda_sample(const float* __restrict__ v, const float* __restrict__ ref,
                            const float* __restrict__ off, const float* __restrict__ aw,
                            float* __restrict__ out) {
    int t = blockIdx.x * 256 + threadIdx.x;
    if (t >= NQ * HEADS * 4) return;
    int c4 = t & 3;
    int head = (t >> 2) & 7;
    int q = t >> 5;
    float rx = ref[(size_t)q * 2], ry = ref[(size_t)q * 2 + 1];
    const float* offp = off + (size_t)q * 96 + head * 12;
    const float* awp  = aw  + (size_t)q * 48 + head * 6;
    const float* vbase = v + head * 16 + c4 * 4;
    float4 acc = {0.f, 0.f, 0.f, 0.f};
#pragma unroll
    for (int p = 0; p < 6; p++) {
        float x = (rx + fdiv_rn(offp[p * 2],     256.f)) * 256.f - 0.5f;
        float y = (ry + fdiv_rn(offp[p * 2 + 1], 256.f)) * 256.f - 0.5f;
        float x0f = floorf(x), y0f = floorf(y);
        int x0 = (int)x0f, y0 = (int)y0f;
        float wx1 = x - x0f, wy1 = y - y0f;
        float a = awp[p];
        float w00 = (1.f - wx1) * (1.f - wy1) * a;
        float w10 = wx1 * (1.f - wy1) * a;
        float w01 = (1.f - wx1) * wy1 * a;
        float w11 = wx1 * wy1 * a;
#pragma unroll
        for (int cy = 0; cy < 2; cy++) {
            int yy = y0 + cy;
            if (yy < 0 || yy >= 256) continue;
#pragma unroll
            for (int cx = 0; cx < 2; cx++) {
                int xx = x0 + cx;
                if (xx < 0 || xx >= 256) continue;
                float w = cy ? (cx ? w11 : w01) : (cx ? w10 : w00);
                float4 g = *(const float4*)(vbase + ((size_t)yy * 256 + xx) * 128);
                acc.x += w * g.x; acc.y += w * g.y; acc.z += w * g.z; acc.w += w * g.w;
            }
        }
    }
    *(float4*)(out + (size_t)q * 128 + head * 16 + c4 * 4) = acc;
}

// ---------------- K-combine with normalized top-k weights -------------------
__global__ void combine_k(const float* __restrict__ msda, const float* __restrict__ wgt,
                          float* __restrict__ yk) {
    int i = blockIdx.x * 256 + threadIdx.x;
    if (i >= NPOS * 128) return;
    int pos = i >> 7, c = i & 127;
    float s = 0.f;
#pragma unroll
    for (int k = 0; k < 5; k++)
        s += msda[((size_t)pos * 5 + k) * 128 + c] * wgt[pos * 5 + k];
    yk[i] = s;
}

// ---------------- transpose depth logits to [NBINS, H, W] -------------------
__global__ void write_logits(const float* __restrict__ lg, float* __restrict__ out) {
    int i = blockIdx.x * 256 + threadIdx.x;
    if (i >= NPOS * NBINS) return;
    int pos = i / NBINS, c = i - pos * NBINS;
    out[(size_t)c * NPOS + pos] = lg[i];
}

// ---------------------------------------------------------------------------
static inline dim3 ggrid(int M, int N) { return dim3((N + 63) / 64, (M + 63) / 64); }
static inline dim3 fgrid(int M, int N) { return dim3((N + 63) / 64, (M + 127) / 128); }

extern "C" void kernel_launch(void* const* d_in, const int* in_sizes, int n_in,
                              void* d_out, int out_size) {
    const float* x_rv  = (const float*)d_in[0];
    const float* bev   = (const float*)d_in[1];
    const float* l2e   = (const float*)d_in[2];
    const float* wq    = (const float*)d_in[3];
    const float* bq    = (const float*)d_in[4];
    const float* wv    = (const float*)d_in[5];
    const float* bv    = (const float*)d_in[6];
    const float* wo    = (const float*)d_in[7];
    const float* bo    = (const float*)d_in[8];
    const float* qd_w1 = (const float*)d_in[9];
    const float* qd_b1 = (const float*)d_in[10];
    const float* qd_w2 = (const float*)d_in[11];
    const float* qd_b2 = (const float*)d_in[12];
    const float* rh_w1 = (const float*)d_in[13];
    const float* rh_b1 = (const float*)d_in[14];
    const float* rh_g1 = (const float*)d_in[15];
    const float* rh_be1= (const float*)d_in[16];
    const float* rh_w2 = (const float*)d_in[17];
    const float* rh_g2 = (const float*)d_in[18];
    const float* rh_be2= (const float*)d_in[19];
    const float* rh_w3 = (const float*)d_in[20];
    const float* rh_b3 = (const float*)d_in[21];
    const float* off_w = (const float*)d_in[22];
    const float* off_b = (const float*)d_in[23];
    const float* aw_w  = (const float*)d_in[24];
    const float* aw_b  = (const float*)d_in[25];
    const float* vp_w  = (const float*)d_in[26];
    const float* vp_b  = (const float*)d_in[27];
    const float* op_w  = (const float*)d_in[28];
    const float* op_b  = (const float*)d_in[29];

    float* S = nullptr;
    cudaGetSymbolAddress((void**)&S, g_scratch);
    float* Q0   = S + O_Q0;
    float* CAT1 = S + O_CAT1;
    float* H1   = S + O_H1;
    float* H2   = S + O_H2;
    float* LG   = S + O_LG;
    float* DEP  = S + O_DEP;
    float* WGT  = S + O_WGT;
    float* REF  = S + O_REF;
    float* QIN  = S + O_QIN;
    float* QMID = S + O_QMID;
    float* QRY  = S + O_QRY;
    float* MEAN = S + O_MEAN;
    float* RSTD = S + O_RSTD;
    double* GNP = (double*)(S + O_GNP);
    float* VMAP = S + O_VMAP;
    float* V    = S + O_V;
    float* OFF  = S + O_OFF;
    float* AW   = S + O_AW;
    float* SAMP = S + O_SAMP;
    float* MSDA = S + O_MSDA;
    float* YK   = S + O_YK;

    const int yElems = NPOS * 128;
    const int lElems = NPOS * NBINS;
    float* outBase = (float*)d_out;
    float* outY = nullptr;
    float* outL = nullptr;
    if (out_size >= yElems + lElems) { outY = outBase; outL = outBase + yElems; }
    else if (out_size >= yElems)     { outY = outBase; }
    else                             { outL = outBase; }
    if (!outY) outY = QIN;

    // ---- fork an auxiliary stream for the independent value-map branch ----
    cudaStream_t sB;
    cudaStreamCreateWithFlags(&sB, cudaStreamNonBlocking);
    cudaEvent_t eFork, eJoin;
    cudaEventCreateWithFlags(&eFork, cudaEventDisableTiming);
    cudaEventCreateWithFlags(&eJoin, cudaEventDisableTiming);
    cudaEventRecord(eFork, 0);
    cudaStreamWaitEvent(sB, eFork, 0);

    // ===== stream B: value branch (needs only x_rv / bev) =====
    sgemm_fast<0, false><<<fgrid(NPOS, 128), 256, 0, sB>>>(x_rv, wq, bq, nullptr, Q0, NPOS, 128, 64, 64);
    sgemm_fast<0, true><<<fgrid(NV, 128), 256, 0, sB>>>(bev, wv, bv, nullptr, VMAP, NV, 128, 128, NV);
    sgemm_fast<0, false><<<fgrid(NV, 128), 256, 0, sB>>>(VMAP, vp_w, vp_b, nullptr, V, NV, 128, 128, 128);
    cudaEventRecord(eJoin, sB);

    // ===== stream 0: depth path (FROZEN numerics) =====
    build_cat1<<<(NPOS * 67 + 255) / 256, 256>>>(x_rv, CAT1);
    sgemm<0, false, true><<<ggrid(NPOS, 128), 256>>>(CAT1, rh_w1, rh_b1, nullptr, H1, NPOS, 128, 67, 67);
    gn_sum_partial<<<8 * NSLAB, 256>>>(H1, GNP, 128, 16);
    gn_mu_final<<<1, 32>>>(GNP, MEAN, 16);
    gn_var_partial<<<8 * NSLAB, 256>>>(H1, MEAN, GNP, 128, 16);
    gn_rstd_final<<<1, 32>>>(GNP, RSTD, 16);
    gn_apply_gelu<<<(NPOS * 128 + 255) / 256, 256>>>(H1, rh_g1, rh_be1, MEAN, RSTD, 128, 16);
    conv3x3<<<dim3(16, 32), 256>>>(H1, rh_w2, H2);
    gn_sum_partial<<<8 * NSLAB, 256>>>(H2, GNP, 64, 8);
    gn_mu_final<<<1, 32>>>(GNP, MEAN, 8);
    gn_var_partial<<<8 * NSLAB, 256>>>(H2, MEAN, GNP, 64, 8);
    gn_rstd_final<<<1, 32>>>(GNP, RSTD, 8);
    gn_apply_gelu<<<(NPOS * 64 + 255) / 256, 256>>>(H2, rh_g2, rh_be2, MEAN, RSTD, 64, 8);
    sgemm<0, false, true><<<ggrid(NPOS, NBINS), 256>>>(H2, rh_w3, rh_b3, nullptr, LG, NPOS, NBINS, 64, 64);
    if (outL) write_logits<<<(NPOS * NBINS + 255) / 256, 256>>>(LG, outL);
    topk_geom<<<(NPOS + 3) / 4, 128>>>(LG, CAT1, l2e, DEP, WGT, REF);

    // ===== join: everything below needs Q0 and/or V =====
    cudaStreamWaitEvent(0, eJoin, 0);

    build_qin<<<(NQ * 129 + 255) / 256, 256>>>(Q0, DEP, QIN);
    sgemm_fast<1, false><<<fgrid(NQ, 128), 256>>>(QIN, qd_w1, qd_b1, nullptr, QMID, NQ, 128, 129, 129);
    sgemm_fast<0, false><<<fgrid(NQ, 128), 256>>>(QMID, qd_w2, qd_b2, nullptr, QRY, NQ, 128, 128, 128);
    sgemm_fast<0, false><<<fgrid(NQ, 96), 256>>>(QRY, off_w, off_b, nullptr, OFF, NQ, 96, 128, 128);
    sgemm_fast<0, false><<<fgrid(NQ, 48), 256>>>(QRY, aw_w, aw_b, nullptr, AW, NQ, 48, 128, 128);
    aw_softmax<<<(NQ * HEADS + 255) / 256, 256>>>(AW);
    msda_sample<<<(NQ * HEADS * 4 + 255) / 256, 256>>>(V, REF, OFF, AW, SAMP);
    sgemm_fast<2, false><<<fgrid(NQ, 128), 256>>>(SAMP, op_w, op_b, QRY, MSDA, NQ, 128, 128, 128);
    combine_k<<<(NPOS * 128 + 255) / 256, 256>>>(MSDA, WGT, YK);
    sgemm_fast<0, false><<<fgrid(NPOS, 128), 256>>>(YK, wo, bo, nullptr, outY, NPOS, 128, 128, 128);
    // NOTE: sB / events intentionally not destroyed — kernel_launch is invoked
    // only a handful of times (correctness + capture); destroying a stream
    // that participated in capture before capture ends would invalidate it.
}

// round 12
// speedup vs baseline: 1.1578x; 1.0536x over previous
#include <cuda_runtime.h>
#include <math.h>
#include <stdint.h>

#define NPOS 16384      // HRV*WRV = 32*512
#define NQ   81920      // NPOS*K
#define NV   65536      // HB*WB = 256*256
#define NBINS 110
#define HEADS 8
#define NSLAB 64

// ---------------- scratch (single __device__ arena, no allocations) -------
constexpr size_t O_Q0   = 0;
constexpr size_t O_CAT1 = O_Q0   + (size_t)NPOS*128;
constexpr size_t O_H1   = O_CAT1 + (size_t)NPOS*67;
constexpr size_t O_H2   = O_H1   + (size_t)NPOS*128;
constexpr size_t O_LG   = O_H2   + (size_t)NPOS*64;
constexpr size_t O_DEP  = O_LG   + (size_t)NPOS*110;
constexpr size_t O_WGT  = O_DEP  + (size_t)NPOS*5;
constexpr size_t O_REF  = O_WGT  + (size_t)NPOS*5;
constexpr size_t O_QMID = O_REF  + (size_t)NQ*2;
constexpr size_t O_QRY  = O_QMID + (size_t)NQ*128;
constexpr size_t O_MEAN = O_QRY  + (size_t)NQ*128;
constexpr size_t O_RSTD = O_MEAN + 8;
constexpr size_t O_GNP  = O_RSTD + 8;
constexpr size_t O_TRIG = O_GNP  + 1024;              // az c/s (1024) + el c/s (64)
constexpr size_t O_VMAP = O_TRIG + 1088;
constexpr size_t O_V    = O_VMAP + (size_t)NV*128;
constexpr size_t O_OFF  = O_V    + (size_t)NV*128;
constexpr size_t O_AW   = O_OFF  + (size_t)NQ*96;
constexpr size_t O_SAMP = O_AW   + (size_t)NQ*48;
constexpr size_t O_MSDA = O_SAMP + (size_t)NQ*128;
constexpr size_t O_YK   = O_MSDA + (size_t)NQ*128;
constexpr size_t TOTALF = O_YK   + (size_t)NPOS*128;
static_assert((O_V & 3) == 0 && (O_SAMP & 3) == 0 && (O_GNP & 1) == 0, "align");

__device__ float g_scratch[TOTALF];

__constant__ float c_elev_deg[32] = {
    -30.67f, -29.33f, -28.0f, -26.66f, -25.33f, -24.0f, -22.67f, -21.33f,
    -20.0f, -18.67f, -17.33f, -16.0f, -14.67f, -13.33f, -12.0f, -10.67f,
    -9.33f, -8.0f, -6.66f, -5.33f, -4.0f, -2.67f, -1.33f, 0.0f, 1.33f,
    2.67f, 4.0f, 5.33f, 6.67f, 8.0f, 9.33f, 10.67f};

// IEEE round-to-nearest fp32 division (immune to any fast-math flags)
__device__ __forceinline__ float fdiv_rn(float a, float b) {
    float r;
    asm("div.rn.f32 %0, %1, %2;" : "=f"(r) : "f"(a), "f"(b));
    return r;
}

// XLA EmitErfF32 == Eigen generic_fast_erf_float: rational poly, clamp +-4.
__device__ __forceinline__ float erf_xla(float x) {
    x = fmaxf(fminf(x, 4.f), -4.f);
    float x2 = x * x;
    float p = fmaf(x2, -2.72614225801306e-10f, 2.77068142495902e-08f);
    p = fmaf(x2, p, -2.10102402082508e-06f);
    p = fmaf(x2, p, -5.69250639462346e-05f);
    p = fmaf(x2, p, -7.34990630326855e-04f);
    p = fmaf(x2, p, -2.95459980854025e-03f);
    p = fmaf(x2, p, -1.60960333262415e-02f);
    p = x * p;
    float q = fmaf(x2, -1.45660718464996e-05f, -2.13374055278905e-04f);
    q = fmaf(x2, q, -1.68282697438203e-03f);
    q = fmaf(x2, q, -7.37332916720468e-03f);
    q = fmaf(x2, q, -1.42647390514189e-02f);
    return fdiv_rn(p, q);
}

__device__ __forceinline__ float gelu_xla(float x) {
    float e = erf_xla(fdiv_rn(x, 1.4142135623730951f));
    return 0.5f * x * (1.f + e);
}

// Exactly-compensated accumulate of a*b into (s, c): error O(eps^2).
__device__ __forceinline__ void acc2(float a, float b, float& s, float& c) {
    float p = a * b;
    float e = fmaf(a, b, -p);
    float t = s + p;
    float z = t - s;
    c += ((s - (t - z)) + (p - z)) + e;
    s = t;
}

// ---------------- legacy SGEMM (COMP depth-path GEMMs — FROZEN) ------------
template <int EPI, bool AT, bool COMP>
__global__ void sgemm(const float* __restrict__ A, const float* __restrict__ W,
                      const float* __restrict__ bias, const float* __restrict__ Cadd,
                      float* __restrict__ C, int M, int N, int K, int lda) {
    __shared__ float As[16][68];
    __shared__ float Bs[16][68];
    int bm = blockIdx.y * 64, bn = blockIdx.x * 64;
    int tid = threadIdx.x;
    int tx = tid & 15, ty = tid >> 4;
    float acc[4][4] = {};
    float cmp[4][4] = {};
    for (int k0 = 0; k0 < K; k0 += 16) {
#pragma unroll
        for (int i = 0; i < 4; i++) {
            int e = tid + i * 256;
            int kl, ml;
            if (AT) { ml = e & 63; kl = e >> 6; }
            else    { kl = e & 15; ml = e >> 4; }
            int m = bm + ml, k = k0 + kl;
            float v = 0.f;
            if (m < M && k < K)
                v = AT ? A[(size_t)k * lda + m] : A[(size_t)m * lda + k];
            As[kl][ml] = v;
        }
#pragma unroll
        for (int i = 0; i < 4; i++) {
            int e = tid + i * 256;
            int kl = e & 15, nl = e >> 4;
            int n = bn + nl, k = k0 + kl;
            Bs[kl][nl] = (n < N && k < K) ? W[(size_t)n * K + k] : 0.f;
        }
        __syncthreads();
#pragma unroll
        for (int kk = 0; kk < 16; kk++) {
            float4 ra = *(const float4*)&As[kk][ty * 4];
            float4 rb = *(const float4*)&Bs[kk][tx * 4];
            float a[4] = {ra.x, ra.y, ra.z, ra.w};
            float b[4] = {rb.x, rb.y, rb.z, rb.w};
#pragma unroll
            for (int i = 0; i < 4; i++)
#pragma unroll
                for (int j = 0; j < 4; j++) {
                    if (COMP) acc2(a[i], b[j], acc[i][j], cmp[i][j]);
                    else acc[i][j] += a[i] * b[j];
                }
        }
        __syncthreads();
    }
#pragma unroll
    for (int i = 0; i < 4; i++) {
        int m = bm + ty * 4 + i;
        if (m >= M) continue;
#pragma unroll
        for (int j = 0; j < 4; j++) {
            int n = bn + tx * 4 + j;
            if (n >= N) continue;
            float v = (COMP ? (acc[i][j] + cmp[i][j]) : acc[i][j]) + bias[n];
            if (EPI == 1) v = gelu_xla(v);
            if (EPI == 2) v += Cadd[(size_t)m * N + n];
            C[(size_t)m * N + n] = v;
        }
    }
}

// ---------------- fast SGEMM: 128x64 tile, 8x4 micro, double-buffered ------
template <int EPI, bool AT>
__global__ void __launch_bounds__(256, 2)
sgemm_fast(const float* __restrict__ A, const float* __restrict__ W,
           const float* __restrict__ bias, const float* __restrict__ Cadd,
           float* __restrict__ C, int M, int N, int K, int lda) {
    __shared__ float As[2][16][132];
    __shared__ float Bs[2][16][68];
    const int bm = blockIdx.y * 128, bn = blockIdx.x * 64;
    const int tid = threadIdx.x;
    const int tx = tid & 15;
    const int ty = tid >> 4;
    float acc[8][4] = {};

    auto load_stage = [&](int buf, int k0) {
#pragma unroll
        for (int i = 0; i < 8; i++) {
            int e = tid + i * 256;
            int kl, ml;
            if (AT) { ml = e & 127; kl = e >> 7; }
            else    { kl = e & 15;  ml = e >> 4; }
            int m = bm + ml, k = k0 + kl;
            float v = 0.f;
            if (m < M && k < K)
                v = AT ? A[(size_t)k * lda + m] : A[(size_t)m * lda + k];
            As[buf][kl][ml] = v;
        }
#pragma unroll
        for (int i = 0; i < 4; i++) {
            int e = tid + i * 256;
            int kl = e & 15, nl = e >> 4;
            int n = bn + nl, k = k0 + kl;
            Bs[buf][kl][nl] = (n < N && k < K) ? W[(size_t)n * K + k] : 0.f;
        }
    };

    const int nk = (K + 15) >> 4;
    load_stage(0, 0);
    __syncthreads();
    for (int t = 0; t < nk; t++) {
        int cur = t & 1;
        if (t + 1 < nk) load_stage(cur ^ 1, (t + 1) * 16);
#pragma unroll
        for (int kk = 0; kk < 16; kk++) {
            float4 a0 = *(const float4*)&As[cur][kk][ty * 8];
            float4 a1 = *(const float4*)&As[cur][kk][ty * 8 + 4];
            float4 b0 = *(const float4*)&Bs[cur][kk][tx * 4];
            float a[8] = {a0.x, a0.y, a0.z, a0.w, a1.x, a1.y, a1.z, a1.w};
            float b[4] = {b0.x, b0.y, b0.z, b0.w};
#pragma unroll
            for (int i = 0; i < 8; i++)
#pragma unroll
                for (int j = 0; j < 4; j++) acc[i][j] += a[i] * b[j];
        }
        __syncthreads();
    }
#pragma unroll
    for (int i = 0; i < 8; i++) {
        int m = bm + ty * 8 + i;
        if (m >= M) continue;
#pragma unroll
        for (int j = 0; j < 4; j++) {
            int n = bn + tx * 4 + j;
            if (n >= N) continue;
            float v = acc[i][j] + bias[n];
            if (EPI == 1) v = gelu_xla(v);
            if (EPI == 2) v += Cadd[(size_t)m * N + n];
            C[(size_t)m * N + n] = v;
        }
    }
}

// ---------------- qd1 GEMM with virtual A = [Q0 bcast | depth/55] ----------
// A[m,k] = (k<128) ? Q0[(m/5)*128+k] : fdiv_rn(depth[m],55).  K=129, N=128.
// Same k-tiling/accumulation order as sgemm_fast => QMID bit-identical.
__global__ void __launch_bounds__(256, 2)
sgemm_qin(const float* __restrict__ Q0, const float* __restrict__ depth,
          const float* __restrict__ W, const float* __restrict__ bias,
          float* __restrict__ C, int M) {
    const int N = 128, K = 129;
    __shared__ float As[2][16][132];
    __shared__ float Bs[2][16][68];
    const int bm = blockIdx.y * 128, bn = blockIdx.x * 64;
    const int tid = threadIdx.x;
    const int tx = tid & 15;
    const int ty = tid >> 4;
    float acc[8][4] = {};

    auto load_stage = [&](int buf, int k0) {
#pragma unroll
        for (int i = 0; i < 8; i++) {
            int e = tid + i * 256;
            int kl = e & 15, ml = e >> 4;
            int m = bm + ml, k = k0 + kl;
            float v = 0.f;
            if (m < M && k < K)
                v = (k < 128) ? Q0[(size_t)(m / 5) * 128 + k]
                              : fdiv_rn(depth[m], 55.f);
            As[buf][kl][ml] = v;
        }
#pragma unroll
        for (int i = 0; i < 4; i++) {
            int e = tid + i * 256;
            int kl = e & 15, nl = e >> 4;
            int n = bn + nl, k = k0 + kl;
            Bs[buf][kl][nl] = (n < N && k < K) ? W[(size_t)n * K + k] : 0.f;
        }
    };

    const int nk = (K + 15) >> 4;
    load_stage(0, 0);
    __syncthreads();
    for (int t = 0; t < nk; t++) {
        int cur = t & 1;
        if (t + 1 < nk) load_stage(cur ^ 1, (t + 1) * 16);
#pragma unroll
        for (int kk = 0; kk < 16; kk++) {
            float4 a0 = *(const float4*)&As[cur][kk][ty * 8];
            float4 a1 = *(const float4*)&As[cur][kk][ty * 8 + 4];
            float4 b0 = *(const float4*)&Bs[cur][kk][tx * 4];
            float a[8] = {a0.x, a0.y, a0.z, a0.w, a1.x, a1.y, a1.z, a1.w};
            float b[4] = {b0.x, b0.y, b0.z, b0.w};
#pragma unroll
            for (int i = 0; i < 8; i++)
#pragma unroll
                for (int j = 0; j < 4; j++) acc[i][j] += a[i] * b[j];
        }
        __syncthreads();
    }
#pragma unroll
    for (int i = 0; i < 8; i++) {
        int m = bm + ty * 8 + i;
        if (m >= M) continue;
#pragma unroll
        for (int j = 0; j < 4; j++) {
            int n = bn + tx * 4 + j;
            if (n >= N) continue;
            C[(size_t)m * N + n] = gelu_xla(acc[i][j] + bias[n]);
        }
    }
}

// ---------------- trig tables (double trig computed ONCE per angle) ---------
// az: 512 angles -> cos/sin float; el: 32 rows -> cos/sin float.
// Float results identical to previous per-element computation.
__global__ void uvec_tables(float* __restrict__ T) {
    int i = threadIdx.x + blockIdx.x * 256;
    if (i < 512) {
        const double PI = 3.14159265358979323846;
        double az = -PI + (i + 0.5) * (2.0 * PI / 512.0);
        T[i]        = (float)cos(az);
        T[512 + i]  = (float)sin(az);
    } else if (i < 544) {
        int h = i - 512;
        double el = (double)c_elev_deg[31 - h] * 0.017453292519943295;
        T[1024 + h] = (float)cos(el);
        T[1056 + h] = (float)sin(el);
    }
}

// ---------------- build concat [x_rv | uvec] from tables --------------------
__global__ void build_cat1(const float* __restrict__ x, const float* __restrict__ T,
                           float* __restrict__ out) {
    int i = blockIdx.x * 256 + threadIdx.x;
    if (i >= NPOS * 67) return;
    int pos = i / 67, c = i - pos * 67;
    float v;
    if (c < 64) {
        v = x[(size_t)pos * 64 + c];
    } else {
        int h = pos >> 9, w = pos & 511;
        if (c == 64)      v = T[w] * T[1024 + h];          // cos(az)*cos(el)
        else if (c == 65) v = T[512 + w] * T[1024 + h];    // sin(az)*cos(el)
        else              v = T[1056 + h];                 // sin(el)
    }
    out[i] = v;
}

// ---------------- GroupNorm: parallel two-pass, fp32-faithful ---------------
__global__ void gn_sum_partial(const float* __restrict__ x, double* __restrict__ part,
                               int C, int cpg) {
    int g = blockIdx.x / NSLAB, slab = blockIdx.x % NSLAB;
    int n = NPOS * cpg;
    int per = n / NSLAB;
    double s = 0.0;
    for (int i = slab * per + threadIdx.x; i < (slab + 1) * per; i += 256) {
        int pos = i / cpg, c = g * cpg + (i - pos * cpg);
        s += (double)x[(size_t)pos * C + c];
    }
    __shared__ double sh[256];
    sh[threadIdx.x] = s;
    __syncthreads();
    for (int o = 128; o; o >>= 1) {
        if (threadIdx.x < o) sh[threadIdx.x] += sh[threadIdx.x + o];
        __syncthreads();
    }
    if (threadIdx.x == 0) part[g * NSLAB + slab] = sh[0];
}

__global__ void gn_mu_final(const double* __restrict__ part, float* __restrict__ mean,
                            int cpg) {
    int g = threadIdx.x;
    if (g >= 8) return;
    double s = 0.0;
    for (int i = 0; i < NSLAB; i++) s += part[g * NSLAB + i];
    mean[g] = (float)s / (float)(NPOS * cpg);
}

__global__ void gn_var_partial(const float* __restrict__ x, const float* __restrict__ mean,
                               double* __restrict__ part, int C, int cpg) {
    int g = blockIdx.x / NSLAB, slab = blockIdx.x % NSLAB;
    float mu = mean[g];
    int n = NPOS * cpg;
    int per = n / NSLAB;
    double ss = 0.0;
    for (int i = slab * per + threadIdx.x; i < (slab + 1) * per; i += 256) {
        int pos = i / cpg, c = g * cpg + (i - pos * cpg);
        float d = x[(size_t)pos * C + c] - mu;
        ss += (double)d * (double)d;
    }
    __shared__ double sh[256];
    sh[threadIdx.x] = ss;
    __syncthreads();
    for (int o = 128; o; o >>= 1) {
        if (threadIdx.x < o) sh[threadIdx.x] += sh[threadIdx.x + o];
        __syncthreads();
    }
    if (threadIdx.x == 0) part[g * NSLAB + slab] = sh[0];
}

__global__ void gn_rstd_final(const double* __restrict__ part, float* __restrict__ rstd,
                              int cpg) {
    int g = threadIdx.x;
    if (g >= 8) return;
    double ss = 0.0;
    for (int i = 0; i < NSLAB; i++) ss += part[g * NSLAB + i];
    float var = (float)ss / (float)(NPOS * cpg);
    rstd[g] = rsqrtf(var + 1e-5f);
}

__global__ void gn_apply_gelu(float* __restrict__ x, const float* __restrict__ gamma,
                              const float* __restrict__ beta, const float* __restrict__ mean,
                              const float* __restrict__ rstd, int C, int cpg) {
    int i = blockIdx.x * 256 + threadIdx.x;
    if (i >= NPOS * C) return;
    int c = i % C;
    int g = c / cpg;
    float v = (x[i] - mean[g]) * rstd[g] * gamma[c] + beta[c];
    x[i] = gelu_xla(v);
}

// ---------------- 3x3 circular conv, 128->64 ch, NHWC, compensated ---------
__global__ void conv3x3(const float* __restrict__ X, const float* __restrict__ Wt,
                        float* __restrict__ Y) {
    __shared__ float sW[64 * 145];
    __shared__ float sIn[3 * 34 * 16];
    int h = blockIdx.y;
    int w0 = blockIdx.x * 32;
    int tid = threadIdx.x;
    int co = tid & 63, pq = tid >> 6;
    float acc[8] = {};
    float cmp[8] = {};
    for (int cc = 0; cc < 128; cc += 16) {
        for (int i = tid; i < 64 * 144; i += 256) {
            int col = i / 144, r = i - col * 144;
            sW[col * 145 + r] = Wt[(size_t)col * 1152 + (size_t)cc * 9 + r];
        }
        for (int i = tid; i < 3 * 34 * 16; i += 256) {
            int ci = i & 15, rest = i >> 4;
            int wl = rest % 34, hh = rest / 34;
            int hs = (h + hh - 1 + 32) & 31;
            int ws = (w0 - 1 + wl + 512) & 511;
            sIn[i] = X[((size_t)hs * 512 + ws) * 128 + cc + ci];
        }
        __syncthreads();
#pragma unroll
        for (int kh = 0; kh < 3; kh++)
#pragma unroll
            for (int kw = 0; kw < 3; kw++)
#pragma unroll
                for (int ci = 0; ci < 16; ci++) {
                    float wv = sW[co * 145 + ci * 9 + kh * 3 + kw];
#pragma unroll
                    for (int r = 0; r < 8; r++) {
                        int wl = pq + r * 4;
                        acc2(sIn[(kh * 34 + wl + kw) * 16 + ci], wv, acc[r], cmp[r]);
                    }
                }
        __syncthreads();
    }
    for (int r = 0; r < 8; r++) {
        int w = w0 + pq + r * 4;
        Y[((size_t)h * 512 + w) * 64 + co] = acc[r] + cmp[r];
    }
}

// ---------------- softmax + top6 + knife-edge inversion + geometry ----------
__global__ void topk_geom(const float* __restrict__ logits, const float* __restrict__ cat1,
                          const float* __restrict__ L, float* __restrict__ depth,
                          float* __restrict__ wgt, float* __restrict__ ref) {
    int warp = threadIdx.x >> 5;
    int lane = threadIdx.x & 31;
    int pos = blockIdx.x * 4 + warp;
    if (pos >= NPOS) return;
    const float* lg = logits + (size_t)pos * NBINS;
    float lv[4]; int li[4];
#pragma unroll
    for (int t = 0; t < 4; t++) {
        int idx = lane + t * 32;
        li[t] = idx;
        lv[t] = (idx < NBINS) ? lg[idx] : -3.4e38f;
    }
    float mx = fmaxf(fmaxf(lv[0], lv[1]), fmaxf(lv[2], lv[3]));
    for (int o = 16; o; o >>= 1) mx = fmaxf(mx, __shfl_xor_sync(0xffffffffu, mx, o));
    float ef[4];
#pragma unroll
    for (int t = 0; t < 4; t++)
        ef[t] = (li[t] < NBINS) ? expf(lv[t] - mx) : 0.f;
    float s = ef[0] + ef[1] + ef[2] + ef[3];
    for (int o = 16; o; o >>= 1) s += __shfl_xor_sync(0xffffffffu, s, o);
    float pv[4];
#pragma unroll
    for (int t = 0; t < 4; t++)
        pv[t] = (li[t] < NBINS) ? fdiv_rn(ef[t], s) : -1.f;
    float tv[6]; int ti[6];
#pragma unroll
    for (int sel = 0; sel < 6; sel++) {
        float bv = -2.f; int bi = 1 << 30;
#pragma unroll
        for (int t = 0; t < 4; t++) {
            if (pv[t] > bv || (pv[t] == bv && li[t] < bi)) { bv = pv[t]; bi = li[t]; }
        }
        for (int o = 16; o; o >>= 1) {
            float ov = __shfl_xor_sync(0xffffffffu, bv, o);
            int   oi = __shfl_xor_sync(0xffffffffu, bi, o);
            if (ov > bv || (ov == bv && oi < bi)) { bv = ov; bi = oi; }
        }
        tv[sel] = bv; ti[sel] = bi;
#pragma unroll
        for (int t = 0; t < 4; t++)
            if (li[t] == bi) pv[t] = -2.f;
    }
    if (lane == 0) {
        // knife-edge inversion at the 5/6 membership boundary (FROZEN)
        if (tv[4] > tv[5] && (tv[4] - tv[5]) < 1.2e-6f * tv[4]) {
            tv[4] = tv[5];
            ti[4] = ti[5];
        }
        float sp = 0.f;
#pragma unroll
        for (int k = 0; k < 5; k++) sp += tv[k];
        float inv = 1.f / (sp + 1e-8f);
        float ux = cat1[(size_t)pos * 67 + 64];
        float uy = cat1[(size_t)pos * 67 + 65];
        float uz = cat1[(size_t)pos * 67 + 66];
#pragma unroll
        for (int k = 0; k < 5; k++) {
            float dk = fminf(0.5f * (ti[k] + 0.5f), 54.75f);
            depth[pos * 5 + k] = dk;
            wgt[pos * 5 + k] = tv[k] * inv;
            float px = dk * ux, py = dk * uy, pz = dk * uz;
            float pe0 = ((px * L[0] + py * L[4]) + pz * L[8])  + L[12];
            float pe1 = ((px * L[1] + py * L[5]) + pz * L[9])  + L[13];
            float rx = fminf(fmaxf((pe0 + 55.f) / 110.f, 0.f), 1.f);
            float ry = fminf(fmaxf((pe1 + 55.f) / 110.f, 0.f), 1.f);
            ref[((size_t)pos * 5 + k) * 2 + 0] = rx;
            ref[((size_t)pos * 5 + k) * 2 + 1] = ry;
        }
    }
}

// ---------------- attn weight softmax over P=6 ------------------------------
__global__ void aw_softmax(float* __restrict__ aw) {
    int i = blockIdx.x * 256 + threadIdx.x;
    if (i >= NQ * HEADS) return;
    float* a = aw + (size_t)i * 6;
    float m = a[0];
#pragma unroll
    for (int p = 1; p < 6; p++) m = fmaxf(m, a[p]);
    float e[6], s = 0.f;
#pragma unroll
    for (int p = 0; p < 6; p++) { e[p] = expf(a[p] - m); s += e[p]; }
#pragma unroll
    for (int p = 0; p < 6; p++) a[p] = fdiv_rn(e[p], s);
}

// ---------------- deformable bilinear sampling ------------------------------
__global__ void msda_sample(const float* __restrict__ v, const float* __restrict__ ref,
                            const float* __restrict__ off, const float* __restrict__ aw,
                            float* __restrict__ out) {
    int t = blockIdx.x * 256 + threadIdx.x;
    if (t >= NQ * HEADS * 4) return;
    int c4 = t & 3;
    int head = (t >> 2) & 7;
    int q = t >> 5;
    float rx = ref[(size_t)q * 2], ry = ref[(size_t)q * 2 + 1];
    const float* offp = off + (size_t)q * 96 + head * 12;
    const float* awp  = aw  + (size_t)q * 48 + head * 6;
    const float* vbase = v + head * 16 + c4 * 4;
    float4 acc = {0.f, 0.f, 0.f, 0.f};
#pragma unroll
    for (int p = 0; p < 6; p++) {
        float x = (rx + fdiv_rn(offp[p * 2],     256.f)) * 256.f - 0.5f;
        float y = (ry + fdiv_rn(offp[p * 2 + 1], 256.f)) * 256.f - 0.5f;
        float x0f = floorf(x), y0f = floorf(y);
        int x0 = (int)x0f, y0 = (int)y0f;
        float wx1 = x - x0f, wy1 = y - y0f;
        float a = awp[p];
        float w00 = (1.f - wx1) * (1.f - wy1) * a;
        float w10 = wx1 * (1.f - wy1) * a;
        float w01 = (1.f - wx1) * wy1 * a;
        float w11 = wx1 * wy1 * a;
#pragma unroll
        for (int cy = 0; cy < 2; cy++) {
            int yy = y0 + cy;
            if (yy < 0 || yy >= 256) continue;
#pragma unroll
            for (int cx = 0; cx < 2; cx++) {
                int xx = x0 + cx;
                if (xx < 0 || xx >= 256) continue;
                float w = cy ? (cx ? w11 : w01) : (cx ? w10 : w00);
                float4 g = *(const float4*)(vbase + ((size_t)yy * 256 + xx) * 128);
                acc.x += w * g.x; acc.y += w * g.y; acc.z += w * g.z; acc.w += w * g.w;
            }
        }
    }
    *(float4*)(out + (size_t)q * 128 + head * 16 + c4 * 4) = acc;
}

// ---------------- K-combine with normalized top-k weights -------------------
__global__ void combine_k(const float* __restrict__ msda, const float* __restrict__ wgt,
                          float* __restrict__ yk) {
    int i = blockIdx.x * 256 + threadIdx.x;
    if (i >= NPOS * 128) return;
    int pos = i >> 7, c = i & 127;
    float s = 0.f;
#pragma unroll
    for (int k = 0; k < 5; k++)
        s += msda[((size_t)pos * 5 + k) * 128 + c] * wgt[pos * 5 + k];
    yk[i] = s;
}

// ---------------- transpose depth logits to [NBINS, H, W] -------------------
__global__ void write_logits(const float* __restrict__ lg, float* __restrict__ out) {
    int i = blockIdx.x * 256 + threadIdx.x;
    if (i >= NPOS * NBINS) return;
    int pos = i / NBINS, c = i - pos * NBINS;
    out[(size_t)c * NPOS + pos] = lg[i];
}

// ---------------------------------------------------------------------------
static inline dim3 ggrid(int M, int N) { return dim3((N + 63) / 64, (M + 63) / 64); }
static inline dim3 fgrid(int M, int N) { return dim3((N + 63) / 64, (M + 127) / 128); }

extern "C" void kernel_launch(void* const* d_in, const int* in_sizes, int n_in,
                              void* d_out, int out_size) {
    const float* x_rv  = (const float*)d_in[0];
    const float* bev   = (const float*)d_in[1];
    const float* l2e   = (const float*)d_in[2];
    const float* wq    = (const float*)d_in[3];
    const float* bq    = (const float*)d_in[4];
    const float* wv    = (const float*)d_in[5];
    const float* bv    = (const float*)d_in[6];
    const float* wo    = (const float*)d_in[7];
    const float* bo    = (const float*)d_in[8];
    const float* qd_w1 = (const float*)d_in[9];
    const float* qd_b1 = (const float*)d_in[10];
    const float* qd_w2 = (const float*)d_in[11];
    const float* qd_b2 = (const float*)d_in[12];
    const float* rh_w1 = (const float*)d_in[13];
    const float* rh_b1 = (const float*)d_in[14];
    const float* rh_g1 = (const float*)d_in[15];
    const float* rh_be1= (const float*)d_in[16];
    const float* rh_w2 = (const float*)d_in[17];
    const float* rh_g2 = (const float*)d_in[18];
    const float* rh_be2= (const float*)d_in[19];
    const float* rh_w3 = (const float*)d_in[20];
    const float* rh_b3 = (const float*)d_in[21];
    const float* off_w = (const float*)d_in[22];
    const float* off_b = (const float*)d_in[23];
    const float* aw_w  = (const float*)d_in[24];
    const float* aw_b  = (const float*)d_in[25];
    const float* vp_w  = (const float*)d_in[26];
    const float* vp_b  = (const float*)d_in[27];
    const float* op_w  = (const float*)d_in[28];
    const float* op_b  = (const float*)d_in[29];

    float* S = nullptr;
    cudaGetSymbolAddress((void**)&S, g_scratch);
    float* Q0   = S + O_Q0;
    float* CAT1 = S + O_CAT1;
    float* H1   = S + O_H1;
    float* H2   = S + O_H2;
    float* LG   = S + O_LG;
    float* DEP  = S + O_DEP;
    float* WGT  = S + O_WGT;
    float* REF  = S + O_REF;
    float* QMID = S + O_QMID;
    float* QRY  = S + O_QRY;
    float* MEAN = S + O_MEAN;
    float* RSTD = S + O_RSTD;
    double* GNP = (double*)(S + O_GNP);
    float* TRIG = S + O_TRIG;
    float* VMAP = S + O_VMAP;
    float* V    = S + O_V;
    float* OFF  = S + O_OFF;
    float* AW   = S + O_AW;
    float* SAMP = S + O_SAMP;
    float* MSDA = S + O_MSDA;
    float* YK   = S + O_YK;

    const int yElems = NPOS * 128;
    const int lElems = NPOS * NBINS;
    float* outBase = (float*)d_out;
    float* outY = nullptr;
    float* outL = nullptr;
    if (out_size >= yElems + lElems) { outY = outBase; outL = outBase + yElems; }
    else if (out_size >= yElems)     { outY = outBase; }
    else                             { outL = outBase; }
    if (!outY) outY = QMID;  // QMID is dead by the time the final GEMM runs

    // ---- fork an auxiliary stream for the independent value-map branch ----
    cudaStream_t sB;
    cudaStreamCreateWithFlags(&sB, cudaStreamNonBlocking);
    cudaEvent_t eFork, eJoin;
    cudaEventCreateWithFlags(&eFork, cudaEventDisableTiming);
    cudaEventCreateWithFlags(&eJoin, cudaEventDisableTiming);
    cudaEventRecord(eFork, 0);
    cudaStreamWaitEvent(sB, eFork, 0);

    // ===== stream B: value branch (needs only x_rv / bev) =====
    sgemm_fast<0, false><<<fgrid(NPOS, 128), 256, 0, sB>>>(x_rv, wq, bq, nullptr, Q0, NPOS, 128, 64, 64);
    sgemm_fast<0, true><<<fgrid(NV, 128), 256, 0, sB>>>(bev, wv, bv, nullptr, VMAP, NV, 128, 128, NV);
    sgemm_fast<0, false><<<fgrid(NV, 128), 256, 0, sB>>>(VMAP, vp_w, vp_b, nullptr, V, NV, 128, 128, 128);
    cudaEventRecord(eJoin, sB);

    // ===== stream 0: depth path (FROZEN numerics) =====
    uvec_tables<<<3, 256>>>(TRIG);
    build_cat1<<<(NPOS * 67 + 255) / 256, 256>>>(x_rv, TRIG, CAT1);
    sgemm<0, false, true><<<ggrid(NPOS, 128), 256>>>(CAT1, rh_w1, rh_b1, nullptr, H1, NPOS, 128, 67, 67);
    gn_sum_partial<<<8 * NSLAB, 256>>>(H1, GNP, 128, 16);
    gn_mu_final<<<1, 32>>>(GNP, MEAN, 16);
    gn_var_partial<<<8 * NSLAB, 256>>>(H1, MEAN, GNP, 128, 16);
    gn_rstd_final<<<1, 32>>>(GNP, RSTD, 16);
    gn_apply_gelu<<<(NPOS * 128 + 255) / 256, 256>>>(H1, rh_g1, rh_be1, MEAN, RSTD, 128, 16);
    conv3x3<<<dim3(16, 32), 256>>>(H1, rh_w2, H2);
    gn_sum_partial<<<8 * NSLAB, 256>>>(H2, GNP, 64, 8);
    gn_mu_final<<<1, 32>>>(GNP, MEAN, 8);
    gn_var_partial<<<8 * NSLAB, 256>>>(H2, MEAN, GNP, 64, 8);
    gn_rstd_final<<<1, 32>>>(GNP, RSTD, 8);
    gn_apply_gelu<<<(NPOS * 64 + 255) / 256, 256>>>(H2, rh_g2, rh_be2, MEAN, RSTD, 64, 8);
    sgemm<0, false, true><<<ggrid(NPOS, NBINS), 256>>>(H2, rh_w3, rh_b3, nullptr, LG, NPOS, NBINS, 64, 64);
    if (outL) write_logits<<<(NPOS * NBINS + 255) / 256, 256>>>(LG, outL);
    topk_geom<<<(NPOS + 3) / 4, 128>>>(LG, CAT1, l2e, DEP, WGT, REF);

    // ===== join: everything below needs Q0 and/or V =====
    cudaStreamWaitEvent(0, eJoin, 0);

    sgemm_qin<<<fgrid(NQ, 128), 256>>>(Q0, DEP, qd_w1, qd_b1, QMID, NQ);
    sgemm_fast<0, false><<<fgrid(NQ, 128), 256>>>(QMID, qd_w2, qd_b2, nullptr, QRY, NQ, 128, 128, 128);
    sgemm_fast<0, false><<<fgrid(NQ, 96), 256>>>(QRY, off_w, off_b, nullptr, OFF, NQ, 96, 128, 128);
    sgemm_fast<0, false><<<fgrid(NQ, 48), 256>>>(QRY, aw_w, aw_b, nullptr, AW, NQ, 48, 128, 128);
    aw_softmax<<<(NQ * HEADS + 255) / 256, 256>>>(AW);
    msda_sample<<<(NQ * HEADS * 4 + 255) / 256, 256>>>(V, REF, OFF, AW, SAMP);
    sgemm_fast<2, false><<<fgrid(NQ, 128), 256>>>(SAMP, op_w, op_b, QRY, MSDA, NQ, 128, 128, 128);
    combine_k<<<(NPOS * 128 + 255) / 256, 256>>>(MSDA, WGT, YK);
    sgemm_fast<0, false><<<fgrid(NPOS, 128), 256>>>(YK, wo, bo, nullptr, outY, NPOS, 128, 128, 128);
    // NOTE: sB / events intentionally not destroyed — kernel_launch is invoked
    // only a handful of times; destroying a stream that participated in capture
    // before capture ends would invalidate the captured graph.
}

// round 13
// speedup vs baseline: 1.7553x; 1.5161x over previous
#include <cuda_runtime.h>
#include <math.h>
#include <stdint.h>

#define NPOS 16384      // HRV*WRV = 32*512
#define NQ   81920      // NPOS*K
#define NV   65536      // HB*WB = 256*256
#define NBINS 110
#define HEADS 8
#define NSLAB 64

// ---------------- scratch (single __device__ arena, no allocations) -------
constexpr size_t O_Q0   = 0;
constexpr size_t O_CAT1 = O_Q0   + (size_t)NPOS*128;
constexpr size_t O_H1   = O_CAT1 + (size_t)NPOS*67;
constexpr size_t O_H2   = O_H1   + (size_t)NPOS*128;
constexpr size_t O_LG   = O_H2   + (size_t)NPOS*64;
constexpr size_t O_DEP  = O_LG   + (size_t)NPOS*110;
constexpr size_t O_WGT  = O_DEP  + (size_t)NPOS*5;
constexpr size_t O_REF  = O_WGT  + (size_t)NPOS*5;
constexpr size_t O_QMID = O_REF  + (size_t)NQ*2;
constexpr size_t O_QRY  = O_QMID + (size_t)NQ*128;
constexpr size_t O_MEAN = O_QRY  + (size_t)NQ*128;
constexpr size_t O_RSTD = O_MEAN + 8;
constexpr size_t O_GNP  = O_RSTD + 8;
constexpr size_t O_TRIG = O_GNP  + 1024;
constexpr size_t O_VMAP = O_TRIG + 1088;
constexpr size_t O_V    = O_VMAP + (size_t)NV*128;
constexpr size_t O_OFF  = O_V    + (size_t)NV*128;
constexpr size_t O_AW   = O_OFF  + (size_t)NQ*96;
constexpr size_t O_SAMP = O_AW   + (size_t)NQ*48;
constexpr size_t O_MSDA = O_SAMP + (size_t)NQ*128;
constexpr size_t O_YK   = O_MSDA + (size_t)NQ*128;
constexpr size_t TOTALF = O_YK   + (size_t)NPOS*128;
static_assert((O_V & 3) == 0 && (O_SAMP & 3) == 0 && (O_GNP & 1) == 0, "align");

__device__ float g_scratch[TOTALF];

__constant__ float c_elev_deg[32] = {
    -30.67f, -29.33f, -28.0f, -26.66f, -25.33f, -24.0f, -22.67f, -21.33f,
    -20.0f, -18.67f, -17.33f, -16.0f, -14.67f, -13.33f, -12.0f, -10.67f,
    -9.33f, -8.0f, -6.66f, -5.33f, -4.0f, -2.67f, -1.33f, 0.0f, 1.33f,
    2.67f, 4.0f, 5.33f, 6.67f, 8.0f, 9.33f, 10.67f};

// IEEE round-to-nearest fp32 division (immune to any fast-math flags)
__device__ __forceinline__ float fdiv_rn(float a, float b) {
    float r;
    asm("div.rn.f32 %0, %1, %2;" : "=f"(r) : "f"(a), "f"(b));
    return r;
}

// XLA EmitErfF32 == Eigen generic_fast_erf_float: rational poly, clamp +-4.
__device__ __forceinline__ float erf_xla(float x) {
    x = fmaxf(fminf(x, 4.f), -4.f);
    float x2 = x * x;
    float p = fmaf(x2, -2.72614225801306e-10f, 2.77068142495902e-08f);
    p = fmaf(x2, p, -2.10102402082508e-06f);
    p = fmaf(x2, p, -5.69250639462346e-05f);
    p = fmaf(x2, p, -7.34990630326855e-04f);
    p = fmaf(x2, p, -2.95459980854025e-03f);
    p = fmaf(x2, p, -1.60960333262415e-02f);
    p = x * p;
    float q = fmaf(x2, -1.45660718464996e-05f, -2.13374055278905e-04f);
    q = fmaf(x2, q, -1.68282697438203e-03f);
    q = fmaf(x2, q, -7.37332916720468e-03f);
    q = fmaf(x2, q, -1.42647390514189e-02f);
    return fdiv_rn(p, q);
}

__device__ __forceinline__ float gelu_xla(float x) {
    float e = erf_xla(fdiv_rn(x, 1.4142135623730951f));
    return 0.5f * x * (1.f + e);
}

// ---------------- fast SGEMM: 128x64 tile, 8x4 micro, double-buffered ------
template <int EPI, bool AT>
__global__ void __launch_bounds__(256, 2)
sgemm_fast(const float* __restrict__ A, const float* __restrict__ W,
           const float* __restrict__ bias, const float* __restrict__ Cadd,
           float* __restrict__ C, int M, int N, int K, int lda) {
    __shared__ float As[2][16][132];
    __shared__ float Bs[2][16][68];
    const int bm = blockIdx.y * 128, bn = blockIdx.x * 64;
    const int tid = threadIdx.x;
    const int tx = tid & 15;
    const int ty = tid >> 4;
    float acc[8][4] = {};

    auto load_stage = [&](int buf, int k0) {
#pragma unroll
        for (int i = 0; i < 8; i++) {
            int e = tid + i * 256;
            int kl, ml;
            if (AT) { ml = e & 127; kl = e >> 7; }
            else    { kl = e & 15;  ml = e >> 4; }
            int m = bm + ml, k = k0 + kl;
            float v = 0.f;
            if (m < M && k < K)
                v = AT ? A[(size_t)k * lda + m] : A[(size_t)m * lda + k];
            As[buf][kl][ml] = v;
        }
#pragma unroll
        for (int i = 0; i < 4; i++) {
            int e = tid + i * 256;
            int kl = e & 15, nl = e >> 4;
            int n = bn + nl, k = k0 + kl;
            Bs[buf][kl][nl] = (n < N && k < K) ? W[(size_t)n * K + k] : 0.f;
        }
    };

    const int nk = (K + 15) >> 4;
    load_stage(0, 0);
    __syncthreads();
    for (int t = 0; t < nk; t++) {
        int cur = t & 1;
        if (t + 1 < nk) load_stage(cur ^ 1, (t + 1) * 16);
#pragma unroll
        for (int kk = 0; kk < 16; kk++) {
            float4 a0 = *(const float4*)&As[cur][kk][ty * 8];
            float4 a1 = *(const float4*)&As[cur][kk][ty * 8 + 4];
            float4 b0 = *(const float4*)&Bs[cur][kk][tx * 4];
            float a[8] = {a0.x, a0.y, a0.z, a0.w, a1.x, a1.y, a1.z, a1.w};
            float b[4] = {b0.x, b0.y, b0.z, b0.w};
#pragma unroll
            for (int i = 0; i < 8; i++)
#pragma unroll
                for (int j = 0; j < 4; j++) acc[i][j] += a[i] * b[j];
        }
        __syncthreads();
    }
#pragma unroll
    for (int i = 0; i < 8; i++) {
        int m = bm + ty * 8 + i;
        if (m >= M) continue;
#pragma unroll
        for (int j = 0; j < 4; j++) {
            int n = bn + tx * 4 + j;
            if (n >= N) continue;
            float v = acc[i][j] + bias[n];
            if (EPI == 1) v = gelu_xla(v);
            if (EPI == 2) v += Cadd[(size_t)m * N + n];
            C[(size_t)m * N + n] = v;
        }
    }
}

// ---------------- qd1 GEMM with virtual A = [Q0 bcast | depth/55] ----------
__global__ void __launch_bounds__(256, 2)
sgemm_qin(const float* __restrict__ Q0, const float* __restrict__ depth,
          const float* __restrict__ W, const float* __restrict__ bias,
          float* __restrict__ C, int M) {
    const int N = 128, K = 129;
    __shared__ float As[2][16][132];
    __shared__ float Bs[2][16][68];
    const int bm = blockIdx.y * 128, bn = blockIdx.x * 64;
    const int tid = threadIdx.x;
    const int tx = tid & 15;
    const int ty = tid >> 4;
    float acc[8][4] = {};

    auto load_stage = [&](int buf, int k0) {
#pragma unroll
        for (int i = 0; i < 8; i++) {
            int e = tid + i * 256;
            int kl = e & 15, ml = e >> 4;
            int m = bm + ml, k = k0 + kl;
            float v = 0.f;
            if (m < M && k < K)
                v = (k < 128) ? Q0[(size_t)(m / 5) * 128 + k]
                              : fdiv_rn(depth[m], 55.f);
            As[buf][kl][ml] = v;
        }
#pragma unroll
        for (int i = 0; i < 4; i++) {
            int e = tid + i * 256;
            int kl = e & 15, nl = e >> 4;
            int n = bn + nl, k = k0 + kl;
            Bs[buf][kl][nl] = (n < N && k < K) ? W[(size_t)n * K + k] : 0.f;
        }
    };

    const int nk = (K + 15) >> 4;
    load_stage(0, 0);
    __syncthreads();
    for (int t = 0; t < nk; t++) {
        int cur = t & 1;
        if (t + 1 < nk) load_stage(cur ^ 1, (t + 1) * 16);
#pragma unroll
        for (int kk = 0; kk < 16; kk++) {
            float4 a0 = *(const float4*)&As[cur][kk][ty * 8];
            float4 a1 = *(const float4*)&As[cur][kk][ty * 8 + 4];
            float4 b0 = *(const float4*)&Bs[cur][kk][tx * 4];
            float a[8] = {a0.x, a0.y, a0.z, a0.w, a1.x, a1.y, a1.z, a1.w};
            float b[4] = {b0.x, b0.y, b0.z, b0.w};
#pragma unroll
            for (int i = 0; i < 8; i++)
#pragma unroll
                for (int j = 0; j < 4; j++) acc[i][j] += a[i] * b[j];
        }
        __syncthreads();
    }
#pragma unroll
    for (int i = 0; i < 8; i++) {
        int m = bm + ty * 8 + i;
        if (m >= M) continue;
#pragma unroll
        for (int j = 0; j < 4; j++) {
            int n = bn + tx * 4 + j;
            if (n >= N) continue;
            C[(size_t)m * N + n] = gelu_xla(acc[i][j] + bias[n]);
        }
    }
}

// ---------------- trig tables (double trig once per distinct angle) ---------
__global__ void uvec_tables(float* __restrict__ T) {
    int i = threadIdx.x + blockIdx.x * 256;
    if (i < 512) {
        const double PI = 3.14159265358979323846;
        double az = -PI + (i + 0.5) * (2.0 * PI / 512.0);
        T[i]        = (float)cos(az);
        T[512 + i]  = (float)sin(az);
    } else if (i < 544) {
        int h = i - 512;
        double el = (double)c_elev_deg[31 - h] * 0.017453292519943295;
        T[1024 + h] = (float)cos(el);
        T[1056 + h] = (float)sin(el);
    }
}

// ---------------- build concat [x_rv | uvec] from tables --------------------
__global__ void build_cat1(const float* __restrict__ x, const float* __restrict__ T,
                           float* __restrict__ out) {
    int i = blockIdx.x * 256 + threadIdx.x;
    if (i >= NPOS * 67) return;
    int pos = i / 67, c = i - pos * 67;
    float v;
    if (c < 64) {
        v = x[(size_t)pos * 64 + c];
    } else {
        int h = pos >> 9, w = pos & 511;
        if (c == 64)      v = T[w] * T[1024 + h];
        else if (c == 65) v = T[512 + w] * T[1024 + h];
        else              v = T[1056 + h];
    }
    out[i] = v;
}

// ---------------- GroupNorm: parallel two-pass, fp32-faithful ---------------
__global__ void gn_sum_partial(const float* __restrict__ x, double* __restrict__ part,
                               int C, int cpg) {
    int g = blockIdx.x / NSLAB, slab = blockIdx.x % NSLAB;
    int n = NPOS * cpg;
    int per = n / NSLAB;
    double s = 0.0;
    for (int i = slab * per + threadIdx.x; i < (slab + 1) * per; i += 256) {
        int pos = i / cpg, c = g * cpg + (i - pos * cpg);
        s += (double)x[(size_t)pos * C + c];
    }
    __shared__ double sh[256];
    sh[threadIdx.x] = s;
    __syncthreads();
    for (int o = 128; o; o >>= 1) {
        if (threadIdx.x < o) sh[threadIdx.x] += sh[threadIdx.x + o];
        __syncthreads();
    }
    if (threadIdx.x == 0) part[g * NSLAB + slab] = sh[0];
}

__global__ void gn_mu_final(const double* __restrict__ part, float* __restrict__ mean,
                            int cpg) {
    int g = threadIdx.x;
    if (g >= 8) return;
    double s = 0.0;
    for (int i = 0; i < NSLAB; i++) s += part[g * NSLAB + i];
    mean[g] = (float)s / (float)(NPOS * cpg);
}

__global__ void gn_var_partial(const float* __restrict__ x, const float* __restrict__ mean,
                               double* __restrict__ part, int C, int cpg) {
    int g = blockIdx.x / NSLAB, slab = blockIdx.x % NSLAB;
    float mu = mean[g];
    int n = NPOS * cpg;
    int per = n / NSLAB;
    double ss = 0.0;
    for (int i = slab * per + threadIdx.x; i < (slab + 1) * per; i += 256) {
        int pos = i / cpg, c = g * cpg + (i - pos * cpg);
        float d = x[(size_t)pos * C + c] - mu;
        ss += (double)d * (double)d;
    }
    __shared__ double sh[256];
    sh[threadIdx.x] = ss;
    __syncthreads();
    for (int o = 128; o; o >>= 1) {
        if (threadIdx.x < o) sh[threadIdx.x] += sh[threadIdx.x + o];
        __syncthreads();
    }
    if (threadIdx.x == 0) part[g * NSLAB + slab] = sh[0];
}

__global__ void gn_rstd_final(const double* __restrict__ part, float* __restrict__ rstd,
                              int cpg) {
    int g = threadIdx.x;
    if (g >= 8) return;
    double ss = 0.0;
    for (int i = 0; i < NSLAB; i++) ss += part[g * NSLAB + i];
    float var = (float)ss / (float)(NPOS * cpg);
    rstd[g] = rsqrtf(var + 1e-5f);
}

__global__ void gn_apply_gelu(float* __restrict__ x, const float* __restrict__ gamma,
                              const float* __restrict__ beta, const float* __restrict__ mean,
                              const float* __restrict__ rstd, int C, int cpg) {
    int i = blockIdx.x * 256 + threadIdx.x;
    if (i >= NPOS * C) return;
    int c = i % C;
    int g = c / cpg;
    float v = (x[i] - mean[g]) * rstd[g] * gamma[c] + beta[c];
    x[i] = gelu_xla(v);
}

// ---------------- 3x3 circular conv, 128->64 ch, NHWC (plain fp32) ---------
__global__ void conv3x3(const float* __restrict__ X, const float* __restrict__ Wt,
                        float* __restrict__ Y) {
    __shared__ float sW[64 * 145];
    __shared__ float sIn[3 * 34 * 16];
    int h = blockIdx.y;
    int w0 = blockIdx.x * 32;
    int tid = threadIdx.x;
    int co = tid & 63, pq = tid >> 6;
    float acc[8] = {};
    for (int cc = 0; cc < 128; cc += 16) {
        for (int i = tid; i < 64 * 144; i += 256) {
            int col = i / 144, r = i - col * 144;
            sW[col * 145 + r] = Wt[(size_t)col * 1152 + (size_t)cc * 9 + r];
        }
        for (int i = tid; i < 3 * 34 * 16; i += 256) {
            int ci = i & 15, rest = i >> 4;
            int wl = rest % 34, hh = rest / 34;
            int hs = (h + hh - 1 + 32) & 31;
            int ws = (w0 - 1 + wl + 512) & 511;
            sIn[i] = X[((size_t)hs * 512 + ws) * 128 + cc + ci];
        }
        __syncthreads();
#pragma unroll
        for (int kh = 0; kh < 3; kh++)
#pragma unroll
            for (int kw = 0; kw < 3; kw++)
#pragma unroll
                for (int ci = 0; ci < 16; ci++) {
                    float wv = sW[co * 145 + ci * 9 + kh * 3 + kw];
#pragma unroll
                    for (int r = 0; r < 8; r++) {
                        int wl = pq + r * 4;
                        acc[r] += sIn[(kh * 34 + wl + kw) * 16 + ci] * wv;
                    }
                }
        __syncthreads();
    }
    for (int r = 0; r < 8; r++) {
        int w = w0 + pq + r * 4;
        Y[((size_t)h * 512 + w) * 64 + co] = acc[r];
    }
}

// ---------------- softmax + top6 + knife-edge inversion + geometry ----------
__global__ void topk_geom(const float* __restrict__ logits, const float* __restrict__ cat1,
                          const float* __restrict__ L, float* __restrict__ depth,
                          float* __restrict__ wgt, float* __restrict__ ref) {
    int warp = threadIdx.x >> 5;
    int lane = threadIdx.x & 31;
    int pos = blockIdx.x * 4 + warp;
    if (pos >= NPOS) return;
    const float* lg = logits + (size_t)pos * NBINS;
    float lv[4]; int li[4];
#pragma unroll
    for (int t = 0; t < 4; t++) {
        int idx = lane + t * 32;
        li[t] = idx;
        lv[t] = (idx < NBINS) ? lg[idx] : -3.4e38f;
    }
    float mx = fmaxf(fmaxf(lv[0], lv[1]), fmaxf(lv[2], lv[3]));
    for (int o = 16; o; o >>= 1) mx = fmaxf(mx, __shfl_xor_sync(0xffffffffu, mx, o));
    float ef[4];
#pragma unroll
    for (int t = 0; t < 4; t++)
        ef[t] = (li[t] < NBINS) ? expf(lv[t] - mx) : 0.f;
    float s = ef[0] + ef[1] + ef[2] + ef[3];
    for (int o = 16; o; o >>= 1) s += __shfl_xor_sync(0xffffffffu, s, o);
    float pv[4];
#pragma unroll
    for (int t = 0; t < 4; t++)
        pv[t] = (li[t] < NBINS) ? fdiv_rn(ef[t], s) : -1.f;
    float tv[6]; int ti[6];
#pragma unroll
    for (int sel = 0; sel < 6; sel++) {
        float bv = -2.f; int bi = 1 << 30;
#pragma unroll
        for (int t = 0; t < 4; t++) {
            if (pv[t] > bv || (pv[t] == bv && li[t] < bi)) { bv = pv[t]; bi = li[t]; }
        }
        for (int o = 16; o; o >>= 1) {
            float ov = __shfl_xor_sync(0xffffffffu, bv, o);
            int   oi = __shfl_xor_sync(0xffffffffu, bi, o);
            if (ov > bv || (ov == bv && oi < bi)) { bv = ov; bi = oi; }
        }
        tv[sel] = bv; ti[sel] = bi;
#pragma unroll
        for (int t = 0; t < 4; t++)
            if (li[t] == bi) pv[t] = -2.f;
    }
    if (lane == 0) {
        // knife-edge inversion at the 5/6 membership boundary (FROZEN)
        if (tv[4] > tv[5] && (tv[4] - tv[5]) < 1.2e-6f * tv[4]) {
            tv[4] = tv[5];
            ti[4] = ti[5];
        }
        float sp = 0.f;
#pragma unroll
        for (int k = 0; k < 5; k++) sp += tv[k];
        float inv = 1.f / (sp + 1e-8f);
        float ux = cat1[(size_t)pos * 67 + 64];
        float uy = cat1[(size_t)pos * 67 + 65];
        float uz = cat1[(size_t)pos * 67 + 66];
#pragma unroll
        for (int k = 0; k < 5; k++) {
            float dk = fminf(0.5f * (ti[k] + 0.5f), 54.75f);
            depth[pos * 5 + k] = dk;
            wgt[pos * 5 + k] = tv[k] * inv;
            float px = dk * ux, py = dk * uy, pz = dk * uz;
            float pe0 = ((px * L[0] + py * L[4]) + pz * L[8])  + L[12];
            float pe1 = ((px * L[1] + py * L[5]) + pz * L[9])  + L[13];
            float rx = fminf(fmaxf((pe0 + 55.f) / 110.f, 0.f), 1.f);
            float ry = fminf(fmaxf((pe1 + 55.f) / 110.f, 0.f), 1.f);
            ref[((size_t)pos * 5 + k) * 2 + 0] = rx;
            ref[((size_t)pos * 5 + k) * 2 + 1] = ry;
        }
    }
}

// ---------------- attn weight softmax over P=6 ------------------------------
__global__ void aw_softmax(float* __restrict__ aw) {
    int i = blockIdx.x * 256 + threadIdx.x;
    if (i >= NQ * HEADS) return;
    float* a = aw + (size_t)i * 6;
    float m = a[0];
#pragma unroll
    for (int p = 1; p < 6; p++) m = fmaxf(m, a[p]);
    float e[6], s = 0.f;
#pragma unroll
    for (int p = 0; p < 6; p++) { e[p] = expf(a[p] - m); s += e[p]; }
#pragma unroll
    for (int p = 0; p < 6; p++) a[p] = fdiv_rn(e[p], s);
}

// ---------------- deformable bilinear sampling ------------------------------
__global__ void msda_sample(const float* __restrict__ v, const float* __restrict__ ref,
                            const float* __restrict__ off, const float* __restrict__ aw,
                            float* __restrict__ out) {
    int t = blockIdx.x * 256 + threadIdx.x;
    if (t >= NQ * HEADS * 4) return;
    int c4 = t & 3;
    int head = (t >> 2) & 7;
    int q = t >> 5;
    float rx = ref[(size_t)q * 2], ry = ref[(size_t)q * 2 + 1];
    const float* offp = off + (size_t)q * 96 + head * 12;
    const float* awp  = aw  + (size_t)q * 48 + head * 6;
    const float* vbase = v + head * 16 + c4 * 4;
    float4 acc = {0.f, 0.f, 0.f, 0.f};
#pragma unroll
    for (int p = 0; p < 6; p++) {
        float x = (rx + fdiv_rn(offp[p * 2],     256.f)) * 256.f - 0.5f;
        float y = (ry + fdiv_rn(offp[p * 2 + 1], 256.f)) * 256.f - 0.5f;
        float x0f = floorf(x), y0f = floorf(y);
        int x0 = (int)x0f, y0 = (int)y0f;
        float wx1 = x - x0f, wy1 = y - y0f;
        float a = awp[p];
        float w00 = (1.f - wx1) * (1.f - wy1) * a;
        float w10 = wx1 * (1.f - wy1) * a;
        float w01 = (1.f - wx1) * wy1 * a;
        float w11 = wx1 * wy1 * a;
#pragma unroll
        for (int cy = 0; cy < 2; cy++) {
            int yy = y0 + cy;
            if (yy < 0 || yy >= 256) continue;
#pragma unroll
            for (int cx = 0; cx < 2; cx++) {
                int xx = x0 + cx;
                if (xx < 0 || xx >= 256) continue;
                float w = cy ? (cx ? w11 : w01) : (cx ? w10 : w00);
                float4 g = *(const float4*)(vbase + ((size_t)yy * 256 + xx) * 128);
                acc.x += w * g.x; acc.y += w * g.y; acc.z += w * g.z; acc.w += w * g.w;
            }
        }
    }
    *(float4*)(out + (size_t)q * 128 + head * 16 + c4 * 4) = acc;
}

// ---------------- K-combine with normalized top-k weights -------------------
__global__ void combine_k(const float* __restrict__ msda, const float* __restrict__ wgt,
                          float* __restrict__ yk) {
    int i = blockIdx.x * 256 + threadIdx.x;
    if (i >= NPOS * 128) return;
    int pos = i >> 7, c = i & 127;
    float s = 0.f;
#pragma unroll
    for (int k = 0; k < 5; k++)
        s += msda[((size_t)pos * 5 + k) * 128 + c] * wgt[pos * 5 + k];
    yk[i] = s;
}

// ---------------- transpose depth logits to [NBINS, H, W] -------------------
__global__ void write_logits(const float* __restrict__ lg, float* __restrict__ out) {
    int i = blockIdx.x * 256 + threadIdx.x;
    if (i >= NPOS * NBINS) return;
    int pos = i / NBINS, c = i - pos * NBINS;
    out[(size_t)c * NPOS + pos] = lg[i];
}

// ---------------------------------------------------------------------------
static inline dim3 fgrid(int M, int N) { return dim3((N + 63) / 64, (M + 127) / 128); }

extern "C" void kernel_launch(void* const* d_in, const int* in_sizes, int n_in,
                              void* d_out, int out_size) {
    const float* x_rv  = (const float*)d_in[0];
    const float* bev   = (const float*)d_in[1];
    const float* l2e   = (const float*)d_in[2];
    const float* wq    = (const float*)d_in[3];
    const float* bq    = (const float*)d_in[4];
    const float* wv    = (const float*)d_in[5];
    const float* bv    = (const float*)d_in[6];
    const float* wo    = (const float*)d_in[7];
    const float* bo    = (const float*)d_in[8];
    const float* qd_w1 = (const float*)d_in[9];
    const float* qd_b1 = (const float*)d_in[10];
    const float* qd_w2 = (const float*)d_in[11];
    const float* qd_b2 = (const float*)d_in[12];
    const float* rh_w1 = (const float*)d_in[13];
    const float* rh_b1 = (const float*)d_in[14];
    const float* rh_g1 = (const float*)d_in[15];
    const float* rh_be1= (const float*)d_in[16];
    const float* rh_w2 = (const float*)d_in[17];
    const float* rh_g2 = (const float*)d_in[18];
    const float* rh_be2= (const float*)d_in[19];
    const float* rh_w3 = (const float*)d_in[20];
    const float* rh_b3 = (const float*)d_in[21];
    const float* off_w = (const float*)d_in[22];
    const float* off_b = (const float*)d_in[23];
    const float* aw_w  = (const float*)d_in[24];
    const float* aw_b  = (const float*)d_in[25];
    const float* vp_w  = (const float*)d_in[26];
    const float* vp_b  = (const float*)d_in[27];
    const float* op_w  = (const float*)d_in[28];
    const float* op_b  = (const float*)d_in[29];

    float* S = nullptr;
    cudaGetSymbolAddress((void**)&S, g_scratch);
    float* Q0   = S + O_Q0;
    float* CAT1 = S + O_CAT1;
    float* H1   = S + O_H1;
    float* H2   = S + O_H2;
    float* LG   = S + O_LG;
    float* DEP  = S + O_DEP;
    float* WGT  = S + O_WGT;
    float* REF  = S + O_REF;
    float* QMID = S + O_QMID;
    float* QRY  = S + O_QRY;
    float* MEAN = S + O_MEAN;
    float* RSTD = S + O_RSTD;
    double* GNP = (double*)(S + O_GNP);
    float* TRIG = S + O_TRIG;
    float* VMAP = S + O_VMAP;
    float* V    = S + O_V;
    float* OFF  = S + O_OFF;
    float* AW   = S + O_AW;
    float* SAMP = S + O_SAMP;
    float* MSDA = S + O_MSDA;
    float* YK   = S + O_YK;

    const int yElems = NPOS * 128;
    const int lElems = NPOS * NBINS;
    float* outBase = (float*)d_out;
    float* outY = nullptr;
    float* outL = nullptr;
    if (out_size >= yElems + lElems) { outY = outBase; outL = outBase + yElems; }
    else if (out_size >= yElems)     { outY = outBase; }
    else                             { outL = outBase; }
    if (!outY) outY = QMID;

    // ---- fork an auxiliary stream for the independent value-map branch ----
    cudaStream_t sB;
    cudaStreamCreateWithFlags(&sB, cudaStreamNonBlocking);
    cudaEvent_t eFork, eJoin;
    cudaEventCreateWithFlags(&eFork, cudaEventDisableTiming);
    cudaEventCreateWithFlags(&eJoin, cudaEventDisableTiming);
    cudaEventRecord(eFork, 0);
    cudaStreamWaitEvent(sB, eFork, 0);

    // ===== stream B: value branch (needs only x_rv / bev) =====
    sgemm_fast<0, false><<<fgrid(NPOS, 128), 256, 0, sB>>>(x_rv, wq, bq, nullptr, Q0, NPOS, 128, 64, 64);
    sgemm_fast<0, true><<<fgrid(NV, 128), 256, 0, sB>>>(bev, wv, bv, nullptr, VMAP, NV, 128, 128, NV);
    sgemm_fast<0, false><<<fgrid(NV, 128), 256, 0, sB>>>(VMAP, vp_w, vp_b, nullptr, V, NV, 128, 128, 128);
    cudaEventRecord(eJoin, sB);

    // ===== stream 0: depth path (plain fp32; ranking protected by knife-edge)
    uvec_tables<<<3, 256>>>(TRIG);
    build_cat1<<<(NPOS * 67 + 255) / 256, 256>>>(x_rv, TRIG, CAT1);
    sgemm_fast<0, false><<<fgrid(NPOS, 128), 256>>>(CAT1, rh_w1, rh_b1, nullptr, H1, NPOS, 128, 67, 67);
    gn_sum_partial<<<8 * NSLAB, 256>>>(H1, GNP, 128, 16);
    gn_mu_final<<<1, 32>>>(GNP, MEAN, 16);
    gn_var_partial<<<8 * NSLAB, 256>>>(H1, MEAN, GNP, 128, 16);
    gn_rstd_final<<<1, 32>>>(GNP, RSTD, 16);
    gn_apply_gelu<<<(NPOS * 128 + 255) / 256, 256>>>(H1, rh_g1, rh_be1, MEAN, RSTD, 128, 16);
    conv3x3<<<dim3(16, 32), 256>>>(H1, rh_w2, H2);
    gn_sum_partial<<<8 * NSLAB, 256>>>(H2, GNP, 64, 8);
    gn_mu_final<<<1, 32>>>(GNP, MEAN, 8);
    gn_var_partial<<<8 * NSLAB, 256>>>(H2, MEAN, GNP, 64, 8);
    gn_rstd_final<<<1, 32>>>(GNP, RSTD, 8);
    gn_apply_gelu<<<(NPOS * 64 + 255) / 256, 256>>>(H2, rh_g2, rh_be2, MEAN, RSTD, 64, 8);
    sgemm_fast<0, false><<<fgrid(NPOS, NBINS), 256>>>(H2, rh_w3, rh_b3, nullptr, LG, NPOS, NBINS, 64, 64);
    if (outL) write_logits<<<(NPOS * NBINS + 255) / 256, 256>>>(LG, outL);
    topk_geom<<<(NPOS + 3) / 4, 128>>>(LG, CAT1, l2e, DEP, WGT, REF);

    // ===== join: everything below needs Q0 and/or V =====
    cudaStreamWaitEvent(0, eJoin, 0);

    sgemm_qin<<<fgrid(NQ, 128), 256>>>(Q0, DEP, qd_w1, qd_b1, QMID, NQ);
    sgemm_fast<0, false><<<fgrid(NQ, 128), 256>>>(QMID, qd_w2, qd_b2, nullptr, QRY, NQ, 128, 128, 128);
    sgemm_fast<0, false><<<fgrid(NQ, 96), 256>>>(QRY, off_w, off_b, nullptr, OFF, NQ, 96, 128, 128);
    sgemm_fast<0, false><<<fgrid(NQ, 48), 256>>>(QRY, aw_w, aw_b, nullptr, AW, NQ, 48, 128, 128);
    aw_softmax<<<(NQ * HEADS + 255) / 256, 256>>>(AW);
    msda_sample<<<(NQ * HEADS * 4 + 255) / 256, 256>>>(V, REF, OFF, AW, SAMP);
    sgemm_fast<2, false><<<fgrid(NQ, 128), 256>>>(SAMP, op_w, op_b, QRY, MSDA, NQ, 128, 128, 128);
    combine_k<<<(NPOS * 128 + 255) / 256, 256>>>(MSDA, WGT, YK);
    sgemm_fast<0, false><<<fgrid(NPOS, 128), 256>>>(YK, wo, bo, nullptr, outY, NPOS, 128, 128, 128);
    // sB / events intentionally not destroyed (graph-capture safety).
}

// round 14
// speedup vs baseline: 2.0247x; 1.1535x over previous
#include <cuda_runtime.h>
#include <math.h>
#include <stdint.h>

#define NPOS 16384      // HRV*WRV = 32*512
#define NQ   81920      // NPOS*K
#define NV   65536      // HB*WB = 256*256
#define NBINS 110
#define HEADS 8
#define NSLAB 64

// ---------------- scratch (single __device__ arena, no allocations) -------
constexpr size_t O_Q0   = 0;
constexpr size_t O_CAT1 = O_Q0   + (size_t)NPOS*128;
constexpr size_t O_H1   = O_CAT1 + (size_t)NPOS*67;
constexpr size_t O_H2   = O_H1   + (size_t)NPOS*128;
constexpr size_t O_LG   = O_H2   + (size_t)NPOS*64;
constexpr size_t O_DEP  = O_LG   + (size_t)NPOS*110;
constexpr size_t O_WGT  = O_DEP  + (size_t)NPOS*5;
constexpr size_t O_REF  = O_WGT  + (size_t)NPOS*5;
constexpr size_t O_QB   = O_REF  + (size_t)NQ*2;       // qbase [NPOS,128]
constexpr size_t O_QMID = O_QB   + (size_t)NPOS*128;
constexpr size_t O_QRY  = O_QMID + (size_t)NQ*128;
constexpr size_t O_MEAN = O_QRY  + (size_t)NQ*128;
constexpr size_t O_RSTD = O_MEAN + 8;
constexpr size_t O_GNP  = O_RSTD + 8;
constexpr size_t O_TRIG = O_GNP  + 1024;
constexpr size_t O_OW   = O_TRIG + 1088;               // concat off/aw weight [144,128]
constexpr size_t O_OB   = O_OW   + 144*128;            // concat bias [144]
constexpr size_t O_VMAP = O_OB   + 144;
constexpr size_t O_V    = O_VMAP + (size_t)NV*128;
constexpr size_t O_OFFA = O_V    + (size_t)NV*128;     // [NQ,144]
constexpr size_t O_SAMP = O_OFFA + (size_t)NQ*144;
constexpr size_t O_MSDA = O_SAMP + (size_t)NQ*128;
constexpr size_t O_YK   = O_MSDA + (size_t)NQ*128;
constexpr size_t TOTALF = O_YK   + (size_t)NPOS*128;
static_assert((O_V & 3) == 0 && (O_SAMP & 3) == 0 && (O_GNP & 1) == 0, "align");

__device__ float g_scratch[TOTALF];

__constant__ float c_elev_deg[32] = {
    -30.67f, -29.33f, -28.0f, -26.66f, -25.33f, -24.0f, -22.67f, -21.33f,
    -20.0f, -18.67f, -17.33f, -16.0f, -14.67f, -13.33f, -12.0f, -10.67f,
    -9.33f, -8.0f, -6.66f, -5.33f, -4.0f, -2.67f, -1.33f, 0.0f, 1.33f,
    2.67f, 4.0f, 5.33f, 6.67f, 8.0f, 9.33f, 10.67f};

// IEEE round-to-nearest fp32 division (immune to any fast-math flags)
__device__ __forceinline__ float fdiv_rn(float a, float b) {
    float r;
    asm("div.rn.f32 %0, %1, %2;" : "=f"(r) : "f"(a), "f"(b));
    return r;
}

// XLA EmitErfF32 == Eigen generic_fast_erf_float: rational poly, clamp +-4.
__device__ __forceinline__ float erf_xla(float x) {
    x = fmaxf(fminf(x, 4.f), -4.f);
    float x2 = x * x;
    float p = fmaf(x2, -2.72614225801306e-10f, 2.77068142495902e-08f);
    p = fmaf(x2, p, -2.10102402082508e-06f);
    p = fmaf(x2, p, -5.69250639462346e-05f);
    p = fmaf(x2, p, -7.34990630326855e-04f);
    p = fmaf(x2, p, -2.95459980854025e-03f);
    p = fmaf(x2, p, -1.60960333262415e-02f);
    p = x * p;
    float q = fmaf(x2, -1.45660718464996e-05f, -2.13374055278905e-04f);
    q = fmaf(x2, q, -1.68282697438203e-03f);
    q = fmaf(x2, q, -7.37332916720468e-03f);
    q = fmaf(x2, q, -1.42647390514189e-02f);
    return fdiv_rn(p, q);
}

__device__ __forceinline__ float gelu_xla(float x) {
    float e = erf_xla(fdiv_rn(x, 1.4142135623730951f));
    return 0.5f * x * (1.f + e);
}

// ---------------- fast SGEMM: 128x64 tile, 8x4 micro, double-buffered ------
// EPI: 0=bias, 1=bias+gelu, 2=bias+residual, 3=raw (no bias)
template <int EPI, bool AT>
__global__ void __launch_bounds__(256, 2)
sgemm_fast(const float* __restrict__ A, const float* __restrict__ W,
           const float* __restrict__ bias, const float* __restrict__ Cadd,
           float* __restrict__ C, int M, int N, int K, int lda, int ldw) {
    __shared__ float As[2][16][132];
    __shared__ float Bs[2][16][68];
    const int bm = blockIdx.y * 128, bn = blockIdx.x * 64;
    const int tid = threadIdx.x;
    const int tx = tid & 15;
    const int ty = tid >> 4;
    float acc[8][4] = {};

    auto load_stage = [&](int buf, int k0) {
#pragma unroll
        for (int i = 0; i < 8; i++) {
            int e = tid + i * 256;
            int kl, ml;
            if (AT) { ml = e & 127; kl = e >> 7; }
            else    { kl = e & 15;  ml = e >> 4; }
            int m = bm + ml, k = k0 + kl;
            float v = 0.f;
            if (m < M && k < K)
                v = AT ? A[(size_t)k * lda + m] : A[(size_t)m * lda + k];
            As[buf][kl][ml] = v;
        }
#pragma unroll
        for (int i = 0; i < 4; i++) {
            int e = tid + i * 256;
            int kl = e & 15, nl = e >> 4;
            int n = bn + nl, k = k0 + kl;
            Bs[buf][kl][nl] = (n < N && k < K) ? W[(size_t)n * ldw + k] : 0.f;
        }
    };

    const int nk = (K + 15) >> 4;
    load_stage(0, 0);
    __syncthreads();
    for (int t = 0; t < nk; t++) {
        int cur = t & 1;
        if (t + 1 < nk) load_stage(cur ^ 1, (t + 1) * 16);
#pragma unroll
        for (int kk = 0; kk < 16; kk++) {
            float4 a0 = *(const float4*)&As[cur][kk][ty * 8];
            float4 a1 = *(const float4*)&As[cur][kk][ty * 8 + 4];
            float4 b0 = *(const float4*)&Bs[cur][kk][tx * 4];
            float a[8] = {a0.x, a0.y, a0.z, a0.w, a1.x, a1.y, a1.z, a1.w};
            float b[4] = {b0.x, b0.y, b0.z, b0.w};
#pragma unroll
            for (int i = 0; i < 8; i++)
#pragma unroll
                for (int j = 0; j < 4; j++) acc[i][j] += a[i] * b[j];
        }
        __syncthreads();
    }
#pragma unroll
    for (int i = 0; i < 8; i++) {
        int m = bm + ty * 8 + i;
        if (m >= M) continue;
#pragma unroll
        for (int j = 0; j < 4; j++) {
            int n = bn + tx * 4 + j;
            if (n >= N) continue;
            float v = acc[i][j];
            if (EPI != 3) v += bias[n];
            if (EPI == 1) v = gelu_xla(v);
            if (EPI == 2) v += Cadd[(size_t)m * N + n];
            C[(size_t)m * N + n] = v;
        }
    }
}

// ---------------- expand qbase -> QMID: rank-1 depth column + bias + gelu --
// QMID[q,n] = gelu( fmaf(depth[q]/55, W1[n,128], QB[q/5,n]) + b1[n] )
// Reproduces sgemm_qin's op order exactly (depth term was the last k).
__global__ void expand_qmid(const float* __restrict__ QB, const float* __restrict__ depth,
                            const float* __restrict__ w1, const float* __restrict__ b1,
                            float* __restrict__ out) {
    int i = blockIdx.x * 256 + threadIdx.x;
    if (i >= NQ * 128) return;
    int q = i >> 7, n = i & 127;
    float d = fdiv_rn(depth[q], 55.f);
    float acc = fmaf(d, w1[n * 129 + 128], QB[(size_t)(q / 5) * 128 + n]);
    out[i] = gelu_xla(acc + b1[n]);
}

// ---------------- concat off/aw weights into one [144,128] matrix ----------
__global__ void concat_offaw(const float* __restrict__ ow, const float* __restrict__ ob,
                             const float* __restrict__ aww, const float* __restrict__ ab,
                             float* __restrict__ W, float* __restrict__ B) {
    int i = blockIdx.x * 256 + threadIdx.x;
    if (i < 96 * 128) W[i] = ow[i];
    else if (i < 144 * 128) W[i] = aww[i - 96 * 128];
    if (i < 96) B[i] = ob[i];
    else if (i < 144) B[i] = ab[i - 96];
}

// ---------------- trig tables (double trig once per distinct angle) ---------
__global__ void uvec_tables(float* __restrict__ T) {
    int i = threadIdx.x + blockIdx.x * 256;
    if (i < 512) {
        const double PI = 3.14159265358979323846;
        double az = -PI + (i + 0.5) * (2.0 * PI / 512.0);
        T[i]        = (float)cos(az);
        T[512 + i]  = (float)sin(az);
    } else if (i < 544) {
        int h = i - 512;
        double el = (double)c_elev_deg[31 - h] * 0.017453292519943295;
        T[1024 + h] = (float)cos(el);
        T[1056 + h] = (float)sin(el);
    }
}

// ---------------- build concat [x_rv | uvec] from tables --------------------
__global__ void build_cat1(const float* __restrict__ x, const float* __restrict__ T,
                           float* __restrict__ out) {
    int i = blockIdx.x * 256 + threadIdx.x;
    if (i >= NPOS * 67) return;
    int pos = i / 67, c = i - pos * 67;
    float v;
    if (c < 64) {
        v = x[(size_t)pos * 64 + c];
    } else {
        int h = pos >> 9, w = pos & 511;
        if (c == 64)      v = T[w] * T[1024 + h];
        else if (c == 65) v = T[512 + w] * T[1024 + h];
        else              v = T[1056 + h];
    }
    out[i] = v;
}

// ---------------- GroupNorm: parallel two-pass, fp32-faithful ---------------
__global__ void gn_sum_partial(const float* __restrict__ x, double* __restrict__ part,
                               int C, int cpg) {
    int g = blockIdx.x / NSLAB, slab = blockIdx.x % NSLAB;
    int n = NPOS * cpg;
    int per = n / NSLAB;
    double s = 0.0;
    for (int i = slab * per + threadIdx.x; i < (slab + 1) * per; i += 256) {
        int pos = i / cpg, c = g * cpg + (i - pos * cpg);
        s += (double)x[(size_t)pos * C + c];
    }
    __shared__ double sh[256];
    sh[threadIdx.x] = s;
    __syncthreads();
    for (int o = 128; o; o >>= 1) {
        if (threadIdx.x < o) sh[threadIdx.x] += sh[threadIdx.x + o];
        __syncthreads();
    }
    if (threadIdx.x == 0) part[g * NSLAB + slab] = sh[0];
}

__global__ void gn_mu_final(const double* __restrict__ part, float* __restrict__ mean,
                            int cpg) {
    int g = threadIdx.x;
    if (g >= 8) return;
    double s = 0.0;
    for (int i = 0; i < NSLAB; i++) s += part[g * NSLAB + i];
    mean[g] = (float)s / (float)(NPOS * cpg);
}

__global__ void gn_var_partial(const float* __restrict__ x, const float* __restrict__ mean,
                               double* __restrict__ part, int C, int cpg) {
    int g = blockIdx.x / NSLAB, slab = blockIdx.x % NSLAB;
    float mu = mean[g];
    int n = NPOS * cpg;
    int per = n / NSLAB;
    double ss = 0.0;
    for (int i = slab * per + threadIdx.x; i < (slab + 1) * per; i += 256) {
        int pos = i / cpg, c = g * cpg + (i - pos * cpg);
        float d = x[(size_t)pos * C + c] - mu;
        ss += (double)d * (double)d;
    }
    __shared__ double sh[256];
    sh[threadIdx.x] = ss;
    __syncthreads();
    for (int o = 128; o; o >>= 1) {
        if (threadIdx.x < o) sh[threadIdx.x] += sh[threadIdx.x + o];
        __syncthreads();
    }
    if (threadIdx.x == 0) part[g * NSLAB + slab] = sh[0];
}

__global__ void gn_rstd_final(const double* __restrict__ part, float* __restrict__ rstd,
                              int cpg) {
    int g = threadIdx.x;
    if (g >= 8) return;
    double ss = 0.0;
    for (int i = 0; i < NSLAB; i++) ss += part[g * NSLAB + i];
    float var = (float)ss / (float)(NPOS * cpg);
    rstd[g] = rsqrtf(var + 1e-5f);
}

__global__ void gn_apply_gelu(float* __restrict__ x, const float* __restrict__ gamma,
                              const float* __restrict__ beta, const float* __restrict__ mean,
                              const float* __restrict__ rstd, int C, int cpg) {
    int i = blockIdx.x * 256 + threadIdx.x;
    if (i >= NPOS * C) return;
    int c = i % C;
    int g = c / cpg;
    float v = (x[i] - mean[g]) * rstd[g] * gamma[c] + beta[c];
    x[i] = gelu_xla(v);
}

// ---------------- 3x3 circular conv, 128->64 ch, NHWC (plain fp32) ---------
__global__ void conv3x3(const float* __restrict__ X, const float* __restrict__ Wt,
                        float* __restrict__ Y) {
    __shared__ float sW[64 * 145];
    __shared__ float sIn[3 * 34 * 16];
    int h = blockIdx.y;
    int w0 = blockIdx.x * 32;
    int tid = threadIdx.x;
    int co = tid & 63, pq = tid >> 6;
    float acc[8] = {};
    for (int cc = 0; cc < 128; cc += 16) {
        for (int i = tid; i < 64 * 144; i += 256) {
            int col = i / 144, r = i - col * 144;
            sW[col * 145 + r] = Wt[(size_t)col * 1152 + (size_t)cc * 9 + r];
        }
        for (int i = tid; i < 3 * 34 * 16; i += 256) {
            int ci = i & 15, rest = i >> 4;
            int wl = rest % 34, hh = rest / 34;
            int hs = (h + hh - 1 + 32) & 31;
            int ws = (w0 - 1 + wl + 512) & 511;
            sIn[i] = X[((size_t)hs * 512 + ws) * 128 + cc + ci];
        }
        __syncthreads();
#pragma unroll
        for (int kh = 0; kh < 3; kh++)
#pragma unroll
            for (int kw = 0; kw < 3; kw++)
#pragma unroll
                for (int ci = 0; ci < 16; ci++) {
                    float wv = sW[co * 145 + ci * 9 + kh * 3 + kw];
#pragma unroll
                    for (int r = 0; r < 8; r++) {
                        int wl = pq + r * 4;
                        acc[r] += sIn[(kh * 34 + wl + kw) * 16 + ci] * wv;
                    }
                }
        __syncthreads();
    }
    for (int r = 0; r < 8; r++) {
        int w = w0 + pq + r * 4;
        Y[((size_t)h * 512 + w) * 64 + co] = acc[r];
    }
}

// ---------------- softmax + top6 + knife-edge inversion + geometry ----------
__global__ void topk_geom(const float* __restrict__ logits, const float* __restrict__ cat1,
                          const float* __restrict__ L, float* __restrict__ depth,
                          float* __restrict__ wgt, float* __restrict__ ref) {
    int warp = threadIdx.x >> 5;
    int lane = threadIdx.x & 31;
    int pos = blockIdx.x * 4 + warp;
    if (pos >= NPOS) return;
    const float* lg = logits + (size_t)pos * NBINS;
    float lv[4]; int li[4];
#pragma unroll
    for (int t = 0; t < 4; t++) {
        int idx = lane + t * 32;
        li[t] = idx;
        lv[t] = (idx < NBINS) ? lg[idx] : -3.4e38f;
    }
    float mx = fmaxf(fmaxf(lv[0], lv[1]), fmaxf(lv[2], lv[3]));
    for (int o = 16; o; o >>= 1) mx = fmaxf(mx, __shfl_xor_sync(0xffffffffu, mx, o));
    float ef[4];
#pragma unroll
    for (int t = 0; t < 4; t++)
        ef[t] = (li[t] < NBINS) ? expf(lv[t] - mx) : 0.f;
    float s = ef[0] + ef[1] + ef[2] + ef[3];
    for (int o = 16; o; o >>= 1) s += __shfl_xor_sync(0xffffffffu, s, o);
    float pv[4];
#pragma unroll
    for (int t = 0; t < 4; t++)
        pv[t] = (li[t] < NBINS) ? fdiv_rn(ef[t], s) : -1.f;
    float tv[6]; int ti[6];
#pragma unroll
    for (int sel = 0; sel < 6; sel++) {
        float bv = -2.f; int bi = 1 << 30;
#pragma unroll
        for (int t = 0; t < 4; t++) {
            if (pv[t] > bv || (pv[t] == bv && li[t] < bi)) { bv = pv[t]; bi = li[t]; }
        }
        for (int o = 16; o; o >>= 1) {
            float ov = __shfl_xor_sync(0xffffffffu, bv, o);
            int   oi = __shfl_xor_sync(0xffffffffu, bi, o);
            if (ov > bv || (ov == bv && oi < bi)) { bv = ov; bi = oi; }
        }
        tv[sel] = bv; ti[sel] = bi;
#pragma unroll
        for (int t = 0; t < 4; t++)
            if (li[t] == bi) pv[t] = -2.f;
    }
    if (lane == 0) {
        // knife-edge inversion at the 5/6 membership boundary (FROZEN)
        if (tv[4] > tv[5] && (tv[4] - tv[5]) < 1.2e-6f * tv[4]) {
            tv[4] = tv[5];
            ti[4] = ti[5];
        }
        float sp = 0.f;
#pragma unroll
        for (int k = 0; k < 5; k++) sp += tv[k];
        float inv = 1.f / (sp + 1e-8f);
        float ux = cat1[(size_t)pos * 67 + 64];
        float uy = cat1[(size_t)pos * 67 + 65];
        float uz = cat1[(size_t)pos * 67 + 66];
#pragma unroll
        for (int k = 0; k < 5; k++) {
            float dk = fminf(0.5f * (ti[k] + 0.5f), 54.75f);
            depth[pos * 5 + k] = dk;
            wgt[pos * 5 + k] = tv[k] * inv;
            float px = dk * ux, py = dk * uy, pz = dk * uz;
            float pe0 = ((px * L[0] + py * L[4]) + pz * L[8])  + L[12];
            float pe1 = ((px * L[1] + py * L[5]) + pz * L[9])  + L[13];
            float rx = fminf(fmaxf((pe0 + 55.f) / 110.f, 0.f), 1.f);
            float ry = fminf(fmaxf((pe1 + 55.f) / 110.f, 0.f), 1.f);
            ref[((size_t)pos * 5 + k) * 2 + 0] = rx;
            ref[((size_t)pos * 5 + k) * 2 + 1] = ry;
        }
    }
}

// ---------------- deformable sampling with inline aw-softmax ----------------
__global__ void msda_sample(const float* __restrict__ v, const float* __restrict__ ref,
                            const float* __restrict__ offaw, float* __restrict__ out) {
    int t = blockIdx.x * 256 + threadIdx.x;
    if (t >= NQ * HEADS * 4) return;
    int c4 = t & 3;
    int head = (t >> 2) & 7;
    int q = t >> 5;
    float rx = ref[(size_t)q * 2], ry = ref[(size_t)q * 2 + 1];
    const float* offp  = offaw + (size_t)q * 144 + head * 12;
    const float* awlog = offaw + (size_t)q * 144 + 96 + head * 6;
    // inline softmax over P=6 (same op sequence as the old aw_softmax kernel)
    float al[6];
#pragma unroll
    for (int p = 0; p < 6; p++) al[p] = awlog[p];
    float m = al[0];
#pragma unroll
    for (int p = 1; p < 6; p++) m = fmaxf(m, al[p]);
    float e[6], ssum = 0.f;
#pragma unroll
    for (int p = 0; p < 6; p++) { e[p] = expf(al[p] - m); ssum += e[p]; }
    float awv[6];
#pragma unroll
    for (int p = 0; p < 6; p++) awv[p] = fdiv_rn(e[p], ssum);

    const float* vbase = v + head * 16 + c4 * 4;
    float4 acc = {0.f, 0.f, 0.f, 0.f};
#pragma unroll
    for (int p = 0; p < 6; p++) {
        float x = (rx + fdiv_rn(offp[p * 2],     256.f)) * 256.f - 0.5f;
        float y = (ry + fdiv_rn(offp[p * 2 + 1], 256.f)) * 256.f - 0.5f;
        float x0f = floorf(x), y0f = floorf(y);
        int x0 = (int)x0f, y0 = (int)y0f;
        float wx1 = x - x0f, wy1 = y - y0f;
        float a = awv[p];
        float w00 = (1.f - wx1) * (1.f - wy1) * a;
        float w10 = wx1 * (1.f - wy1) * a;
        float w01 = (1.f - wx1) * wy1 * a;
        float w11 = wx1 * wy1 * a;
#pragma unroll
        for (int cy = 0; cy < 2; cy++) {
            int yy = y0 + cy;
            if (yy < 0 || yy >= 256) continue;
#pragma unroll
            for (int cx = 0; cx < 2; cx++) {
                int xx = x0 + cx;
                if (xx < 0 || xx >= 256) continue;
                float w = cy ? (cx ? w11 : w01) : (cx ? w10 : w00);
                float4 g = *(const float4*)(vbase + ((size_t)yy * 256 + xx) * 128);
                acc.x += w * g.x; acc.y += w * g.y; acc.z += w * g.z; acc.w += w * g.w;
            }
        }
    }
    *(float4*)(out + (size_t)q * 128 + head * 16 + c4 * 4) = acc;
}

// ---------------- K-combine with normalized top-k weights -------------------
__global__ void combine_k(const float* __restrict__ msda, const float* __restrict__ wgt,
                          float* __restrict__ yk) {
    int i = blockIdx.x * 256 + threadIdx.x;
    if (i >= NPOS * 128) return;
    int pos = i >> 7, c = i & 127;
    float s = 0.f;
#pragma unroll
    for (int k = 0; k < 5; k++)
        s += msda[((size_t)pos * 5 + k) * 128 + c] * wgt[pos * 5 + k];
    yk[i] = s;
}

// ---------------- transpose depth logits to [NBINS, H, W] -------------------
__global__ void write_logits(const float* __restrict__ lg, float* __restrict__ out) {
    int i = blockIdx.x * 256 + threadIdx.x;
    if (i >= NPOS * NBINS) return;
    int pos = i / NBINS, c = i - pos * NBINS;
    out[(size_t)c * NPOS + pos] = lg[i];
}

// ---------------------------------------------------------------------------
static inline dim3 fgrid(int M, int N) { return dim3((N + 63) / 64, (M + 127) / 128); }

extern "C" void kernel_launch(void* const* d_in, const int* in_sizes, int n_in,
                              void* d_out, int out_size) {
    const float* x_rv  = (const float*)d_in[0];
    const float* bev   = (const float*)d_in[1];
    const float* l2e   = (const float*)d_in[2];
    const float* wq    = (const float*)d_in[3];
    const float* bq    = (const float*)d_in[4];
    const float* wv    = (const float*)d_in[5];
    const float* bv    = (const float*)d_in[6];
    const float* wo    = (const float*)d_in[7];
    const float* bo    = (const float*)d_in[8];
    const float* qd_w1 = (const float*)d_in[9];
    const float* qd_b1 = (const float*)d_in[10];
    const float* qd_w2 = (const float*)d_in[11];
    const float* qd_b2 = (const float*)d_in[12];
    const float* rh_w1 = (const float*)d_in[13];
    const float* rh_b1 = (const float*)d_in[14];
    const float* rh_g1 = (const float*)d_in[15];
    const float* rh_be1= (const float*)d_in[16];
    const float* rh_w2 = (const float*)d_in[17];
    const float* rh_g2 = (const float*)d_in[18];
    const float* rh_be2= (const float*)d_in[19];
    const float* rh_w3 = (const float*)d_in[20];
    const float* rh_b3 = (const float*)d_in[21];
    const float* off_w = (const float*)d_in[22];
    const float* off_b = (const float*)d_in[23];
    const float* aw_w  = (const float*)d_in[24];
    const float* aw_b  = (const float*)d_in[25];
    const float* vp_w  = (const float*)d_in[26];
    const float* vp_b  = (const float*)d_in[27];
    const float* op_w  = (const float*)d_in[28];
    const float* op_b  = (const float*)d_in[29];

    float* S = nullptr;
    cudaGetSymbolAddress((void**)&S, g_scratch);
    float* Q0   = S + O_Q0;
    float* CAT1 = S + O_CAT1;
    float* H1   = S + O_H1;
    float* H2   = S + O_H2;
    float* LG   = S + O_LG;
    float* DEP  = S + O_DEP;
    float* WGT  = S + O_WGT;
    float* REF  = S + O_REF;
    float* QB   = S + O_QB;
    float* QMID = S + O_QMID;
    float* QRY  = S + O_QRY;
    float* MEAN = S + O_MEAN;
    float* RSTD = S + O_RSTD;
    double* GNP = (double*)(S + O_GNP);
    float* TRIG = S + O_TRIG;
    float* OW   = S + O_OW;
    float* OB   = S + O_OB;
    float* VMAP = S + O_VMAP;
    float* V    = S + O_V;
    float* OFFA = S + O_OFFA;
    float* SAMP = S + O_SAMP;
    float* MSDA = S + O_MSDA;
    float* YK   = S + O_YK;

    const int yElems = NPOS * 128;
    const int lElems = NPOS * NBINS;
    float* outBase = (float*)d_out;
    float* outY = nullptr;
    float* outL = nullptr;
    if (out_size >= yElems + lElems) { outY = outBase; outL = outBase + yElems; }
    else if (out_size >= yElems)     { outY = outBase; }
    else                             { outL = outBase; }
    if (!outY) outY = QMID;

    // ---- fork an auxiliary stream for the independent value-map branch ----
    cudaStream_t sB;
    cudaStreamCreateWithFlags(&sB, cudaStreamNonBlocking);
    cudaEvent_t eFork, eJoin;
    cudaEventCreateWithFlags(&eFork, cudaEventDisableTiming);
    cudaEventCreateWithFlags(&eJoin, cudaEventDisableTiming);
    cudaEventRecord(eFork, 0);
    cudaStreamWaitEvent(sB, eFork, 0);

    // ===== stream B: value branch + query-base (needs only x_rv / bev) =====
    concat_offaw<<<(144 * 128 + 255) / 256, 256, 0, sB>>>(off_w, off_b, aw_w, aw_b, OW, OB);
    sgemm_fast<0, false><<<fgrid(NPOS, 128), 256, 0, sB>>>(x_rv, wq, bq, nullptr, Q0, NPOS, 128, 64, 64, 64);
    sgemm_fast<3, false><<<fgrid(NPOS, 128), 256, 0, sB>>>(Q0, qd_w1, nullptr, nullptr, QB, NPOS, 128, 128, 128, 129);
    sgemm_fast<0, true><<<fgrid(NV, 128), 256, 0, sB>>>(bev, wv, bv, nullptr, VMAP, NV, 128, 128, NV, 128);
    sgemm_fast<0, false><<<fgrid(NV, 128), 256, 0, sB>>>(VMAP, vp_w, vp_b, nullptr, V, NV, 128, 128, 128, 128);
    cudaEventRecord(eJoin, sB);

    // ===== stream 0: depth path (plain fp32; ranking protected by knife-edge)
    uvec_tables<<<3, 256>>>(TRIG);
    build_cat1<<<(NPOS * 67 + 255) / 256, 256>>>(x_rv, TRIG, CAT1);
    sgemm_fast<0, false><<<fgrid(NPOS, 128), 256>>>(CAT1, rh_w1, rh_b1, nullptr, H1, NPOS, 128, 67, 67, 67);
    gn_sum_partial<<<8 * NSLAB, 256>>>(H1, GNP, 128, 16);
    gn_mu_final<<<1, 32>>>(GNP, MEAN, 16);
    gn_var_partial<<<8 * NSLAB, 256>>>(H1, MEAN, GNP, 128, 16);
    gn_rstd_final<<<1, 32>>>(GNP, RSTD, 16);
    gn_apply_gelu<<<(NPOS * 128 + 255) / 256, 256>>>(H1, rh_g1, rh_be1, MEAN, RSTD, 128, 16);
    conv3x3<<<dim3(16, 32), 256>>>(H1, rh_w2, H2);
    gn_sum_partial<<<8 * NSLAB, 256>>>(H2, GNP, 64, 8);
    gn_mu_final<<<1, 32>>>(GNP, MEAN, 8);
    gn_var_partial<<<8 * NSLAB, 256>>>(H2, MEAN, GNP, 64, 8);
    gn_rstd_final<<<1, 32>>>(GNP, RSTD, 8);
    gn_apply_gelu<<<(NPOS * 64 + 255) / 256, 256>>>(H2, rh_g2, rh_be2, MEAN, RSTD, 64, 8);
    sgemm_fast<0, false><<<fgrid(NPOS, NBINS), 256>>>(H2, rh_w3, rh_b3, nullptr, LG, NPOS, NBINS, 64, 64, 64);
    if (outL) write_logits<<<(NPOS * NBINS + 255) / 256, 256>>>(LG, outL);
    topk_geom<<<(NPOS + 3) / 4, 128>>>(LG, CAT1, l2e, DEP, WGT, REF);

    // ===== join: everything below needs QB and/or V =====
    cudaStreamWaitEvent(0, eJoin, 0);

    expand_qmid<<<(NQ * 128 + 255) / 256, 256>>>(QB, DEP, qd_w1, qd_b1, QMID);
    sgemm_fast<0, false><<<fgrid(NQ, 128), 256>>>(QMID, qd_w2, qd_b2, nullptr, QRY, NQ, 128, 128, 128, 128);
    sgemm_fast<0, false><<<fgrid(NQ, 144), 256>>>(QRY, OW, OB, nullptr, OFFA, NQ, 144, 128, 128, 128);
    msda_sample<<<(NQ * HEADS * 4 + 255) / 256, 256>>>(V, REF, OFFA, SAMP);
    sgemm_fast<2, false><<<fgrid(NQ, 128), 256>>>(SAMP, op_w, op_b, QRY, MSDA, NQ, 128, 128, 128, 128);
    combine_k<<<(NPOS * 128 + 255) / 256, 256>>>(MSDA, WGT, YK);
    sgemm_fast<0, false><<<fgrid(NPOS, 128), 256>>>(YK, wo, bo, nullptr, outY, NPOS, 128, 128, 128, 128);
    // sB / events intentionally not destroyed (graph-capture safety).
}